// round 1
// baseline (speedup 1.0000x reference)
#include <cuda_runtime.h>

#define BB 2
#define SS 2048
#define DD 2048
#define NHH 16
#define NKVV 4
#define HDD 128
#define QDIM 2048
#define KVDIM 512
#define QKVD 3072
#define MROWS (BB*SS)   // 4096

// Scratch (no cudaMalloc allowed)
__device__ float g_qkv[(size_t)MROWS * QKVD];   // [B*S, 3072]
__device__ float g_attn[(size_t)MROWS * QDIM];  // [B*S, 2048]

// ---------------------------------------------------------------------------
// NT GEMM: C[M,N] = A[M,K] * B[N,K]^T   (both operands K-contiguous)
// 64x64 block tile, BK=16, 256 threads, 4x4 per thread.
// ---------------------------------------------------------------------------
#define GBK 16
#define GLD (GBK + 1)

__global__ __launch_bounds__(256) void gemm_nt_kernel(
    const float* __restrict__ A, const float* __restrict__ B,
    float* __restrict__ C, int M, int N, int K)
{
    __shared__ float sA[64 * GLD];
    __shared__ float sB[64 * GLD];

    int tid = threadIdx.x;
    int tx = tid & 15, ty = tid >> 4;
    int m0 = blockIdx.y * 64, n0 = blockIdx.x * 64;

    float acc[4][4] = {};

    for (int k0 = 0; k0 < K; k0 += GBK) {
        #pragma unroll
        for (int e = 0; e < 4; e++) {
            int i = tid + e * 256;          // 0..1023
            int r = i >> 4, c = i & 15;
            sA[r * GLD + c] = A[(size_t)(m0 + r) * K + k0 + c];
            sB[r * GLD + c] = B[(size_t)(n0 + r) * K + k0 + c];
        }
        __syncthreads();

        #pragma unroll
        for (int kk = 0; kk < GBK; kk++) {
            float a[4], b[4];
            #pragma unroll
            for (int i2 = 0; i2 < 4; i2++) a[i2] = sA[(ty * 4 + i2) * GLD + kk];
            #pragma unroll
            for (int j = 0; j < 4; j++)   b[j]  = sB[(tx * 4 + j) * GLD + kk];
            #pragma unroll
            for (int i2 = 0; i2 < 4; i2++)
                #pragma unroll
                for (int j = 0; j < 4; j++)
                    acc[i2][j] += a[i2] * b[j];
        }
        __syncthreads();
    }

    #pragma unroll
    for (int i2 = 0; i2 < 4; i2++)
        #pragma unroll
        for (int j = 0; j < 4; j++)
            C[(size_t)(m0 + ty * 4 + i2) * N + n0 + tx * 4 + j] = acc[i2][j];
}

// ---------------------------------------------------------------------------
// RoPE (in-place on g_qkv, q heads 0..15 and k heads 16..19)
// out[2i]   = t0*f1 - t1*f0
// out[2i+1] = t0*f0 + t1*f1
// ---------------------------------------------------------------------------
__global__ __launch_bounds__(256) void rope_kernel(
    float* __restrict__ qkv, const float* __restrict__ freqs)
{
    int idx = blockIdx.x * blockDim.x + threadIdx.x;   // B*S*20*64 threads
    int i    = idx & 63;                 // pair index within head dim
    int head = (idx >> 6) % 20;          // 0..15 = q heads, 16..19 = k heads
    int bs   = idx / (64 * 20);          // 0..4095
    int s    = bs & (SS - 1);

    int off = (head < NHH) ? head * HDD : QDIM + (head - NHH) * HDD;
    size_t base = (size_t)bs * QKVD + off + 2 * i;

    float t0 = qkv[base], t1 = qkv[base + 1];
    float f0 = freqs[s * HDD + 2 * i];
    float f1 = freqs[s * HDD + 2 * i + 1];
    qkv[base]     = t0 * f1 - t1 * f0;
    qkv[base + 1] = t0 * f0 + t1 * f1;
}

// ---------------------------------------------------------------------------
// Causal flash attention, fp32, GQA (kvh = h>>2).
// 64 q-rows x 64 k-cols tiles, HD=128. K and V share one smem buffer
// (sequential use) so smem = 83.2 KB -> 2 CTAs/SM.
// QK^T: 16x16 threads, 4x4 each. PV: thread owns rows ty*4..+3, cols tx+16*i.
// ---------------------------------------------------------------------------
#define AQ  129   // padded row stride for 128-wide tiles (conflict control)
#define ASr 65    // padded row stride for 64-wide score tile
#define ATTN_SMEM_FLOATS (64*AQ + 64*AQ + 64*ASr + 64 + 64)
#define ATTN_SMEM_BYTES  (ATTN_SMEM_FLOATS * 4)

__global__ __launch_bounds__(256) void attn_kernel(
    const float* __restrict__ qkv, float* __restrict__ attn)
{
    extern __shared__ float sm[];
    float* sQ     = sm;                   // [64][129]
    float* sKV    = sQ + 64 * AQ;         // [64][129]  (K, then V)
    float* sS     = sKV + 64 * AQ;        // [64][65]
    float* sAlpha = sS + 64 * ASr;        // [64]
    float* sInvL  = sAlpha + 64;          // [64]

    int tid = threadIdx.x;
    int tx = tid & 15, ty = tid >> 4;
    int qt = (SS / 64 - 1) - blockIdx.x;  // reverse order: big blocks first
    int h  = blockIdx.y, b = blockIdx.z;
    int kvh = h >> 2;
    int q0 = qt * 64;
    const float scale = 0.08838834764831845f;  // 1/sqrt(128)

    // ---- load Q tile ----
    const float* qbase = qkv + ((size_t)(b * SS + q0)) * QKVD + h * HDD;
    #pragma unroll
    for (int e = 0; e < 8; e++) {
        int i = tid + e * 256;            // 0..2047, 4 floats each
        int r = i >> 5, c = (i & 31) << 2;
        float4 v = *(const float4*)(qbase + (size_t)r * QKVD + c);
        float* d = &sQ[r * AQ + c];
        d[0] = v.x; d[1] = v.y; d[2] = v.z; d[3] = v.w;
    }

    float m_i = -1e30f, l_i = 0.f;
    float o[4][8];
    #pragma unroll
    for (int r = 0; r < 4; r++)
        #pragma unroll
        for (int i = 0; i < 8; i++) o[r][i] = 0.f;

    for (int kt = 0; kt <= qt; kt++) {
        int k0 = kt * 64;
        const float* kbase = qkv + ((size_t)(b * SS + k0)) * QKVD + QDIM + kvh * HDD;
        const float* vbase = kbase + KVDIM;  // V is 512 floats after K within a row

        __syncthreads();  // previous iter done reading sKV(V)/sS

        // ---- load K ----
        #pragma unroll
        for (int e = 0; e < 8; e++) {
            int i = tid + e * 256;
            int r = i >> 5, c = (i & 31) << 2;
            float4 v = *(const float4*)(kbase + (size_t)r * QKVD + c);
            float* d = &sKV[r * AQ + c];
            d[0] = v.x; d[1] = v.y; d[2] = v.z; d[3] = v.w;
        }
        __syncthreads();

        // ---- S = scale * Q K^T (+ causal mask) ----
        float sacc[4][4] = {};
        #pragma unroll 8
        for (int kk = 0; kk < HDD; kk++) {
            float a[4], bq[4];
            #pragma unroll
            for (int i = 0; i < 4; i++) a[i]  = sQ[(ty * 4 + i) * AQ + kk];
            #pragma unroll
            for (int j = 0; j < 4; j++) bq[j] = sKV[(tx * 4 + j) * AQ + kk];
            #pragma unroll
            for (int i = 0; i < 4; i++)
                #pragma unroll
                for (int j = 0; j < 4; j++)
                    sacc[i][j] += a[i] * bq[j];
        }
        bool diag = (kt == qt);
        #pragma unroll
        for (int i = 0; i < 4; i++)
            #pragma unroll
            for (int j = 0; j < 4; j++) {
                float sv = sacc[i][j] * scale;
                if (diag && (k0 + tx * 4 + j > q0 + ty * 4 + i)) sv = -1e30f;
                sS[(ty * 4 + i) * ASr + tx * 4 + j] = sv;
            }
        __syncthreads();  // S complete; everyone done reading K

        // ---- load V (reuse sKV) + row softmax update (concurrent) ----
        #pragma unroll
        for (int e = 0; e < 8; e++) {
            int i = tid + e * 256;
            int r = i >> 5, c = (i & 31) << 2;
            float4 v = *(const float4*)(vbase + (size_t)r * QKVD + c);
            float* d = &sKV[r * AQ + c];
            d[0] = v.x; d[1] = v.y; d[2] = v.z; d[3] = v.w;
        }
        if (tid < 64) {
            int row = tid;
            float rowmax = -1e30f;
            #pragma unroll 8
            for (int k = 0; k < 64; k++) rowmax = fmaxf(rowmax, sS[row * ASr + k]);
            float mnew = fmaxf(m_i, rowmax);
            float alpha = __expf(m_i - mnew);
            float lsum = 0.f;
            #pragma unroll 8
            for (int k = 0; k < 64; k++) {
                float p = __expf(sS[row * ASr + k] - mnew);
                sS[row * ASr + k] = p;
                lsum += p;
            }
            l_i = l_i * alpha + lsum;
            m_i = mnew;
            sAlpha[row] = alpha;
        }
        __syncthreads();

        // ---- O = O*alpha + P V ----
        float al[4];
        #pragma unroll
        for (int r = 0; r < 4; r++) al[r] = sAlpha[ty * 4 + r];
        #pragma unroll
        for (int r = 0; r < 4; r++)
            #pragma unroll
            for (int i = 0; i < 8; i++) o[r][i] *= al[r];

        #pragma unroll 4
        for (int k = 0; k < 64; k++) {
            float p[4], vv[8];
            #pragma unroll
            for (int r = 0; r < 4; r++) p[r] = sS[(ty * 4 + r) * ASr + k];
            #pragma unroll
            for (int i = 0; i < 8; i++) vv[i] = sKV[k * AQ + tx + 16 * i];
            #pragma unroll
            for (int r = 0; r < 4; r++)
                #pragma unroll
                for (int i = 0; i < 8; i++)
                    o[r][i] += p[r] * vv[i];
        }
    }

    __syncthreads();
    if (tid < 64) sInvL[tid] = 1.f / l_i;
    __syncthreads();

    #pragma unroll
    for (int r = 0; r < 4; r++) {
        int qg = q0 + ty * 4 + r;
        float inv = sInvL[ty * 4 + r];
        float* op = attn + ((size_t)(b * SS + qg)) * QDIM + h * HDD;
        #pragma unroll
        for (int i = 0; i < 8; i++) op[tx + 16 * i] = o[r][i] * inv;
    }
}

// ---------------------------------------------------------------------------
extern "C" void kernel_launch(void* const* d_in, const int* in_sizes, int n_in,
                              void* d_out, int out_size)
{
    (void)in_sizes; (void)n_in; (void)out_size;
    const float* x     = (const float*)d_in[0];
    const float* freqs = (const float*)d_in[1];
    const float* Wqkv  = (const float*)d_in[2];
    const float* Wo    = (const float*)d_in[3];
    float* out = (float*)d_out;

    float *qkvp, *attnp;
    cudaGetSymbolAddress((void**)&qkvp, g_qkv);
    cudaGetSymbolAddress((void**)&attnp, g_attn);
    cudaFuncSetAttribute(attn_kernel, cudaFuncAttributeMaxDynamicSharedMemorySize,
                         ATTN_SMEM_BYTES);

    // 1) QKV projection: [4096,3072] = x[4096,2048] @ Wqkv[3072,2048]^T
    gemm_nt_kernel<<<dim3(QKVD / 64, MROWS / 64), 256>>>(x, Wqkv, qkvp, MROWS, QKVD, DD);

    // 2) RoPE on q + k in place
    rope_kernel<<<(BB * SS * 20 * 64) / 256, 256>>>(qkvp, freqs);

    // 3) causal GQA flash attention -> g_attn [4096, 2048]
    attn_kernel<<<dim3(SS / 64, NHH, BB), 256, ATTN_SMEM_BYTES>>>(qkvp, attnp);

    // 4) output projection: out[4096,2048] = attn[4096,2048] @ Wo[2048,2048]^T
    gemm_nt_kernel<<<dim3(DD / 64, MROWS / 64), 256>>>(attnp, Wo, out, MROWS, DD, QDIM);
}

// round 2
// speedup vs baseline: 2.0377x; 2.0377x over previous
#include <cuda_runtime.h>

#define BB 2
#define SS 2048
#define DD 2048
#define NHH 16
#define NKVV 4
#define HDD 128
#define QDIM 2048
#define KVDIM 512
#define QKVD 3072
#define MROWS (BB*SS)   // 4096

// Scratch (no cudaMalloc allowed)
__device__ float g_qkv[(size_t)MROWS * QKVD];   // [B*S, 3072]
__device__ float g_attn[(size_t)MROWS * QDIM];  // [B*S, 2048]

// ---------------------------------------------------------------------------
// TF32 tensor-core NT GEMM: C[M,N] = A[M,K] * B[N,K]^T
// 128x128 block tile, BK=32, 256 threads (8 warps, 2x4), 64x32 warp tile.
// mma.sync.m16n8k8 tf32, cp.async double-buffered smem.
// Smem stride 36 floats => fragment gathers hit banks 4g+tc (conflict-free).
// ---------------------------------------------------------------------------
#define TBM 128
#define TBN 128
#define TBK 32
#define TLD 36

__device__ __forceinline__ unsigned cvt_tf32(float x) {
    unsigned r;
    asm("cvt.rna.tf32.f32 %0, %1;" : "=r"(r) : "f"(x));
    return r;
}

__device__ __forceinline__ void mma_tf32(float* c, const unsigned* a, const unsigned* b) {
    asm volatile(
        "mma.sync.aligned.m16n8k8.row.col.f32.tf32.tf32.f32 "
        "{%0,%1,%2,%3},{%4,%5,%6,%7},{%8,%9},{%0,%1,%2,%3};"
        : "+f"(c[0]), "+f"(c[1]), "+f"(c[2]), "+f"(c[3])
        : "r"(a[0]), "r"(a[1]), "r"(a[2]), "r"(a[3]), "r"(b[0]), "r"(b[1]));
}

#define GEMM_SMEM_BYTES (4 * TBM * TLD * 4)   // 2 stages x (A + B) = 73728 B

__global__ __launch_bounds__(256) void gemm_tf32_nt(
    const float* __restrict__ A, const float* __restrict__ B,
    float* __restrict__ C, int M, int N, int K)
{
    extern __shared__ float smem[];
    float* sA = smem;                   // [2][128][36]
    float* sB = smem + 2 * TBM * TLD;   // [2][128][36]

    int tid = threadIdx.x;
    int lane = tid & 31, w = tid >> 5;
    int wm = w >> 2, wn = w & 3;            // warp grid 2 x 4
    int g = lane >> 2, tc = lane & 3;       // groupID, thread-in-group
    int m0 = blockIdx.y * TBM, n0 = blockIdx.x * TBN;

    int lr = tid >> 3;            // 0..31  (row within 32-row pass)
    int lc4 = (tid & 7) << 2;     // float4 col offset: 0..28

    const float* Ag = A + (size_t)(m0 + lr) * K + lc4;
    const float* Bg = B + (size_t)(n0 + lr) * K + lc4;

    float acc[4][4][4] = {};

    auto load_stage = [&](int t, int buf) {
        float* dA = sA + buf * TBM * TLD;
        float* dB = sB + buf * TBM * TLD;
        size_t koff = (size_t)t * TBK;
        #pragma unroll
        for (int i = 0; i < 4; i++) {
            int rr = lr + 32 * i;
            unsigned da = (unsigned)__cvta_generic_to_shared(dA + rr * TLD + lc4);
            asm volatile("cp.async.ca.shared.global [%0], [%1], 16;\n"
                         :: "r"(da), "l"(Ag + (size_t)32 * i * K + koff));
            unsigned db = (unsigned)__cvta_generic_to_shared(dB + rr * TLD + lc4);
            asm volatile("cp.async.ca.shared.global [%0], [%1], 16;\n"
                         :: "r"(db), "l"(Bg + (size_t)32 * i * K + koff));
        }
        asm volatile("cp.async.commit_group;\n");
    };

    int T = K / TBK;
    load_stage(0, 0);

    for (int t = 0; t < T; t++) {
        asm volatile("cp.async.wait_group 0;\n");
        __syncthreads();
        if (t + 1 < T) load_stage(t + 1, (t + 1) & 1);

        const float* cA = sA + (t & 1) * TBM * TLD + (wm * 64) * TLD;
        const float* cB = sB + (t & 1) * TBM * TLD + (wn * 32) * TLD;

        #pragma unroll
        for (int ks = 0; ks < 4; ks++) {
            unsigned a[4][4], b[4][2];
            #pragma unroll
            for (int mf = 0; mf < 4; mf++) {
                const float* ap = cA + (mf * 16 + g) * TLD + ks * 8 + tc;
                a[mf][0] = cvt_tf32(ap[0]);
                a[mf][1] = cvt_tf32(ap[8 * TLD]);
                a[mf][2] = cvt_tf32(ap[4]);
                a[mf][3] = cvt_tf32(ap[8 * TLD + 4]);
            }
            #pragma unroll
            for (int nf = 0; nf < 4; nf++) {
                const float* bp = cB + (nf * 8 + g) * TLD + ks * 8 + tc;
                b[nf][0] = cvt_tf32(bp[0]);
                b[nf][1] = cvt_tf32(bp[4]);
            }
            #pragma unroll
            for (int mf = 0; mf < 4; mf++)
                #pragma unroll
                for (int nf = 0; nf < 4; nf++)
                    mma_tf32(acc[mf][nf], a[mf], b[nf]);
        }
        __syncthreads();
    }

    #pragma unroll
    for (int mf = 0; mf < 4; mf++) {
        #pragma unroll
        for (int nf = 0; nf < 4; nf++) {
            int row = m0 + wm * 64 + mf * 16 + g;
            int col = n0 + wn * 32 + nf * 8 + 2 * tc;
            float* p0 = C + (size_t)row * N + col;
            float* p1 = C + (size_t)(row + 8) * N + col;
            p0[0] = acc[mf][nf][0];
            p0[1] = acc[mf][nf][1];
            p1[0] = acc[mf][nf][2];
            p1[1] = acc[mf][nf][3];
        }
    }
}

// ---------------------------------------------------------------------------
// RoPE (in-place on g_qkv, q heads 0..15 and k heads 16..19)
// ---------------------------------------------------------------------------
__global__ __launch_bounds__(256) void rope_kernel(
    float* __restrict__ qkv, const float* __restrict__ freqs)
{
    int idx = blockIdx.x * blockDim.x + threadIdx.x;
    int i    = idx & 63;
    int head = (idx >> 6) % 20;
    int bs   = idx / (64 * 20);
    int s    = bs & (SS - 1);

    int off = (head < NHH) ? head * HDD : QDIM + (head - NHH) * HDD;
    size_t base = (size_t)bs * QKVD + off + 2 * i;

    float t0 = qkv[base], t1 = qkv[base + 1];
    float f0 = freqs[s * HDD + 2 * i];
    float f1 = freqs[s * HDD + 2 * i + 1];
    qkv[base]     = t0 * f1 - t1 * f0;
    qkv[base + 1] = t0 * f0 + t1 * f1;
}

// ---------------------------------------------------------------------------
// Causal flash attention, fp32, GQA (kvh = h>>2).  (unchanged this round)
// ---------------------------------------------------------------------------
#define AQ  129
#define ASr 65
#define ATTN_SMEM_FLOATS (64*AQ + 64*AQ + 64*ASr + 64 + 64)
#define ATTN_SMEM_BYTES  (ATTN_SMEM_FLOATS * 4)

__global__ __launch_bounds__(256) void attn_kernel(
    const float* __restrict__ qkv, float* __restrict__ attn)
{
    extern __shared__ float sm[];
    float* sQ     = sm;
    float* sKV    = sQ + 64 * AQ;
    float* sS     = sKV + 64 * AQ;
    float* sAlpha = sS + 64 * ASr;
    float* sInvL  = sAlpha + 64;

    int tid = threadIdx.x;
    int tx = tid & 15, ty = tid >> 4;
    int qt = (SS / 64 - 1) - blockIdx.x;
    int h  = blockIdx.y, b = blockIdx.z;
    int kvh = h >> 2;
    int q0 = qt * 64;
    const float scale = 0.08838834764831845f;

    const float* qbase = qkv + ((size_t)(b * SS + q0)) * QKVD + h * HDD;
    #pragma unroll
    for (int e = 0; e < 8; e++) {
        int i = tid + e * 256;
        int r = i >> 5, c = (i & 31) << 2;
        float4 v = *(const float4*)(qbase + (size_t)r * QKVD + c);
        float* d = &sQ[r * AQ + c];
        d[0] = v.x; d[1] = v.y; d[2] = v.z; d[3] = v.w;
    }

    float m_i = -1e30f, l_i = 0.f;
    float o[4][8];
    #pragma unroll
    for (int r = 0; r < 4; r++)
        #pragma unroll
        for (int i = 0; i < 8; i++) o[r][i] = 0.f;

    for (int kt = 0; kt <= qt; kt++) {
        int k0 = kt * 64;
        const float* kbase = qkv + ((size_t)(b * SS + k0)) * QKVD + QDIM + kvh * HDD;
        const float* vbase = kbase + KVDIM;

        __syncthreads();

        #pragma unroll
        for (int e = 0; e < 8; e++) {
            int i = tid + e * 256;
            int r = i >> 5, c = (i & 31) << 2;
            float4 v = *(const float4*)(kbase + (size_t)r * QKVD + c);
            float* d = &sKV[r * AQ + c];
            d[0] = v.x; d[1] = v.y; d[2] = v.z; d[3] = v.w;
        }
        __syncthreads();

        float sacc[4][4] = {};
        #pragma unroll 8
        for (int kk = 0; kk < HDD; kk++) {
            float a[4], bq[4];
            #pragma unroll
            for (int i = 0; i < 4; i++) a[i]  = sQ[(ty * 4 + i) * AQ + kk];
            #pragma unroll
            for (int j = 0; j < 4; j++) bq[j] = sKV[(tx * 4 + j) * AQ + kk];
            #pragma unroll
            for (int i = 0; i < 4; i++)
                #pragma unroll
                for (int j = 0; j < 4; j++)
                    sacc[i][j] += a[i] * bq[j];
        }
        bool diag = (kt == qt);
        #pragma unroll
        for (int i = 0; i < 4; i++)
            #pragma unroll
            for (int j = 0; j < 4; j++) {
                float sv = sacc[i][j] * scale;
                if (diag && (k0 + tx * 4 + j > q0 + ty * 4 + i)) sv = -1e30f;
                sS[(ty * 4 + i) * ASr + tx * 4 + j] = sv;
            }
        __syncthreads();

        #pragma unroll
        for (int e = 0; e < 8; e++) {
            int i = tid + e * 256;
            int r = i >> 5, c = (i & 31) << 2;
            float4 v = *(const float4*)(vbase + (size_t)r * QKVD + c);
            float* d = &sKV[r * AQ + c];
            d[0] = v.x; d[1] = v.y; d[2] = v.z; d[3] = v.w;
        }
        if (tid < 64) {
            int row = tid;
            float rowmax = -1e30f;
            #pragma unroll 8
            for (int k = 0; k < 64; k++) rowmax = fmaxf(rowmax, sS[row * ASr + k]);
            float mnew = fmaxf(m_i, rowmax);
            float alpha = __expf(m_i - mnew);
            float lsum = 0.f;
            #pragma unroll 8
            for (int k = 0; k < 64; k++) {
                float p = __expf(sS[row * ASr + k] - mnew);
                sS[row * ASr + k] = p;
                lsum += p;
            }
            l_i = l_i * alpha + lsum;
            m_i = mnew;
            sAlpha[row] = alpha;
        }
        __syncthreads();

        float al[4];
        #pragma unroll
        for (int r = 0; r < 4; r++) al[r] = sAlpha[ty * 4 + r];
        #pragma unroll
        for (int r = 0; r < 4; r++)
            #pragma unroll
            for (int i = 0; i < 8; i++) o[r][i] *= al[r];

        #pragma unroll 4
        for (int k = 0; k < 64; k++) {
            float p[4], vv[8];
            #pragma unroll
            for (int r = 0; r < 4; r++) p[r] = sS[(ty * 4 + r) * ASr + k];
            #pragma unroll
            for (int i = 0; i < 8; i++) vv[i] = sKV[k * AQ + tx + 16 * i];
            #pragma unroll
            for (int r = 0; r < 4; r++)
                #pragma unroll
                for (int i = 0; i < 8; i++)
                    o[r][i] += p[r] * vv[i];
        }
    }

    __syncthreads();
    if (tid < 64) sInvL[tid] = 1.f / l_i;
    __syncthreads();

    #pragma unroll
    for (int r = 0; r < 4; r++) {
        int qg = q0 + ty * 4 + r;
        float inv = sInvL[ty * 4 + r];
        float* op = attn + ((size_t)(b * SS + qg)) * QDIM + h * HDD;
        #pragma unroll
        for (int i = 0; i < 8; i++) op[tx + 16 * i] = o[r][i] * inv;
    }
}

// ---------------------------------------------------------------------------
extern "C" void kernel_launch(void* const* d_in, const int* in_sizes, int n_in,
                              void* d_out, int out_size)
{
    (void)in_sizes; (void)n_in; (void)out_size;
    const float* x     = (const float*)d_in[0];
    const float* freqs = (const float*)d_in[1];
    const float* Wqkv  = (const float*)d_in[2];
    const float* Wo    = (const float*)d_in[3];
    float* out = (float*)d_out;

    float *qkvp, *attnp;
    cudaGetSymbolAddress((void**)&qkvp, g_qkv);
    cudaGetSymbolAddress((void**)&attnp, g_attn);
    cudaFuncSetAttribute(attn_kernel, cudaFuncAttributeMaxDynamicSharedMemorySize,
                         ATTN_SMEM_BYTES);
    cudaFuncSetAttribute(gemm_tf32_nt, cudaFuncAttributeMaxDynamicSharedMemorySize,
                         GEMM_SMEM_BYTES);

    // 1) QKV projection: [4096,3072] = x @ Wqkv^T
    gemm_tf32_nt<<<dim3(QKVD / TBN, MROWS / TBM), 256, GEMM_SMEM_BYTES>>>(
        x, Wqkv, qkvp, MROWS, QKVD, DD);

    // 2) RoPE on q + k in place
    rope_kernel<<<(BB * SS * 20 * 64) / 256, 256>>>(qkvp, freqs);

    // 3) causal GQA flash attention -> g_attn
    attn_kernel<<<dim3(SS / 64, NHH, BB), 256, ATTN_SMEM_BYTES>>>(qkvp, attnp);

    // 4) output projection: out = attn @ Wo^T
    gemm_tf32_nt<<<dim3(DD / TBN, MROWS / TBM), 256, GEMM_SMEM_BYTES>>>(
        attnp, Wo, out, MROWS, DD, QDIM);
}

// round 3
// speedup vs baseline: 2.6191x; 1.2853x over previous
#include <cuda_runtime.h>

#define BB 2
#define SS 2048
#define DD 2048
#define NHH 16
#define NKVV 4
#define HDD 128
#define QDIM 2048
#define KVDIM 512
#define QKVD 3072
#define MROWS (BB*SS)   // 4096

// Scratch (no cudaMalloc allowed)
__device__ float g_qkv[(size_t)MROWS * QKVD];   // [B*S, 3072]
__device__ float g_attn[(size_t)MROWS * QDIM];  // [B*S, 2048]

// ---------------------------------------------------------------------------
// Common MMA helpers
// ---------------------------------------------------------------------------
__device__ __forceinline__ unsigned cvt_tf32(float x) {
    unsigned r;
    asm("cvt.rna.tf32.f32 %0, %1;" : "=r"(r) : "f"(x));
    return r;
}

__device__ __forceinline__ void mma_tf32(float* c, const unsigned* a, const unsigned* b) {
    asm volatile(
        "mma.sync.aligned.m16n8k8.row.col.f32.tf32.tf32.f32 "
        "{%0,%1,%2,%3},{%4,%5,%6,%7},{%8,%9},{%0,%1,%2,%3};"
        : "+f"(c[0]), "+f"(c[1]), "+f"(c[2]), "+f"(c[3])
        : "r"(a[0]), "r"(a[1]), "r"(a[2]), "r"(a[3]), "r"(b[0]), "r"(b[1]));
}

__device__ __forceinline__ void mma_bf16(float* c, const unsigned* a, const unsigned* b) {
    asm volatile(
        "mma.sync.aligned.m16n8k16.row.col.f32.bf16.bf16.f32 "
        "{%0,%1,%2,%3},{%4,%5,%6,%7},{%8,%9},{%0,%1,%2,%3};"
        : "+f"(c[0]), "+f"(c[1]), "+f"(c[2]), "+f"(c[3])
        : "r"(a[0]), "r"(a[1]), "r"(a[2]), "r"(a[3]), "r"(b[0]), "r"(b[1]));
}

// Split a float2 (adjacent k elements) into packed bf16x2 hi + lo planes.
// hi = truncate-to-bf16 (top 16 bits), lo = rn-bf16(x - hi). Element k -> low half.
__device__ __forceinline__ void split_bf16x3(float2 v, unsigned& hi, unsigned& lo) {
    unsigned x = __float_as_uint(v.x), y = __float_as_uint(v.y);
    asm("prmt.b32 %0, %1, %2, 0x7632;" : "=r"(hi) : "r"(x), "r"(y));
    float lx = v.x - __uint_as_float(x & 0xffff0000u);
    float ly = v.y - __uint_as_float(y & 0xffff0000u);
    asm("cvt.rn.satfinite.bf16x2.f32 %0, %1, %2;" : "=r"(lo) : "f"(ly), "f"(lx));
}

// ---------------------------------------------------------------------------
// bf16x3 tensor-core NT GEMM: C[M,N] = A[M,K] * B[N,K]^T  (~fp32 accuracy)
// 128x128 block tile, BK=32, 256 threads (8 warps, 2x4), 64x32 warp tile.
// ---------------------------------------------------------------------------
#define TBM 128
#define TBN 128
#define TBK 32
#define TLD 36

#define GEMM_SMEM_BYTES (4 * TBM * TLD * 4)   // 2 stages x (A + B) = 73728 B

__global__ __launch_bounds__(256) void gemm_bf16x3_nt(
    const float* __restrict__ A, const float* __restrict__ B,
    float* __restrict__ C, int M, int N, int K)
{
    extern __shared__ float smem[];
    float* sA = smem;                   // [2][128][36]
    float* sB = smem + 2 * TBM * TLD;   // [2][128][36]

    int tid = threadIdx.x;
    int lane = tid & 31, w = tid >> 5;
    int wm = w >> 2, wn = w & 3;            // warp grid 2 x 4
    int g = lane >> 2, tc = lane & 3;
    int m0 = blockIdx.y * TBM, n0 = blockIdx.x * TBN;

    int lr = tid >> 3;            // 0..31
    int lc4 = (tid & 7) << 2;     // 0..28

    const float* Ag = A + (size_t)(m0 + lr) * K + lc4;
    const float* Bg = B + (size_t)(n0 + lr) * K + lc4;

    float acc[4][4][4] = {};

    auto load_stage = [&](int t, int buf) {
        float* dA = sA + buf * TBM * TLD;
        float* dB = sB + buf * TBM * TLD;
        size_t koff = (size_t)t * TBK;
        #pragma unroll
        for (int i = 0; i < 4; i++) {
            int rr = lr + 32 * i;
            unsigned da = (unsigned)__cvta_generic_to_shared(dA + rr * TLD + lc4);
            asm volatile("cp.async.ca.shared.global [%0], [%1], 16;\n"
                         :: "r"(da), "l"(Ag + (size_t)32 * i * K + koff));
            unsigned db = (unsigned)__cvta_generic_to_shared(dB + rr * TLD + lc4);
            asm volatile("cp.async.ca.shared.global [%0], [%1], 16;\n"
                         :: "r"(db), "l"(Bg + (size_t)32 * i * K + koff));
        }
        asm volatile("cp.async.commit_group;\n");
    };

    int T = K / TBK;
    load_stage(0, 0);

    for (int t = 0; t < T; t++) {
        asm volatile("cp.async.wait_group 0;\n");
        __syncthreads();
        if (t + 1 < T) load_stage(t + 1, (t + 1) & 1);

        const float* cA = sA + (t & 1) * TBM * TLD + (wm * 64) * TLD;
        const float* cB = sB + (t & 1) * TBM * TLD + (wn * 32) * TLD;

        #pragma unroll
        for (int ks = 0; ks < 2; ks++) {      // two k16 chunks
            unsigned ahi[4][4], alo[4][4], bhi[4][2], blo[4][2];
            #pragma unroll
            for (int mf = 0; mf < 4; mf++) {
                const float* ap = cA + (mf * 16 + g) * TLD + ks * 16 + 2 * tc;
                split_bf16x3(*(const float2*)(ap),               ahi[mf][0], alo[mf][0]);
                split_bf16x3(*(const float2*)(ap + 8 * TLD),     ahi[mf][1], alo[mf][1]);
                split_bf16x3(*(const float2*)(ap + 8),           ahi[mf][2], alo[mf][2]);
                split_bf16x3(*(const float2*)(ap + 8 * TLD + 8), ahi[mf][3], alo[mf][3]);
            }
            #pragma unroll
            for (int nf = 0; nf < 4; nf++) {
                const float* bp = cB + (nf * 8 + g) * TLD + ks * 16 + 2 * tc;
                split_bf16x3(*(const float2*)(bp),     bhi[nf][0], blo[nf][0]);
                split_bf16x3(*(const float2*)(bp + 8), bhi[nf][1], blo[nf][1]);
            }
            #pragma unroll
            for (int mf = 0; mf < 4; mf++)
                #pragma unroll
                for (int nf = 0; nf < 4; nf++) {
                    mma_bf16(acc[mf][nf], ahi[mf], bhi[nf]);
                    mma_bf16(acc[mf][nf], ahi[mf], blo[nf]);
                    mma_bf16(acc[mf][nf], alo[mf], bhi[nf]);
                }
        }
        __syncthreads();
    }

    #pragma unroll
    for (int mf = 0; mf < 4; mf++) {
        #pragma unroll
        for (int nf = 0; nf < 4; nf++) {
            int row = m0 + wm * 64 + mf * 16 + g;
            int col = n0 + wn * 32 + nf * 8 + 2 * tc;
            float* p0 = C + (size_t)row * N + col;
            float* p1 = C + (size_t)(row + 8) * N + col;
            p0[0] = acc[mf][nf][0];
            p0[1] = acc[mf][nf][1];
            p1[0] = acc[mf][nf][2];
            p1[1] = acc[mf][nf][3];
        }
    }
}

// ---------------------------------------------------------------------------
// RoPE (in-place on g_qkv)
// ---------------------------------------------------------------------------
__global__ __launch_bounds__(256) void rope_kernel(
    float* __restrict__ qkv, const float* __restrict__ freqs)
{
    int idx = blockIdx.x * blockDim.x + threadIdx.x;
    int i    = idx & 63;
    int head = (idx >> 6) % 20;
    int bs   = idx / (64 * 20);
    int s    = bs & (SS - 1);

    int off = (head < NHH) ? head * HDD : QDIM + (head - NHH) * HDD;
    size_t base = (size_t)bs * QKVD + off + 2 * i;

    float t0 = qkv[base], t1 = qkv[base + 1];
    float f0 = freqs[s * HDD + 2 * i];
    float f1 = freqs[s * HDD + 2 * i + 1];
    qkv[base]     = t0 * f1 - t1 * f0;
    qkv[base + 1] = t0 * f0 + t1 * f1;
}

// ---------------------------------------------------------------------------
// Causal flash attention with TF32 tensor cores. GQA kvh = h>>2.
// 64x64 tiles, HD=128. 256 threads, warp grid: wm in [0,4) (16 rows each),
// wn in [0,2) (QK: 32 cols, PV: 64 out-cols each).
// Smem strides: Q/K 132 (=4 mod 32), V 136 (=8 mod 32), S 68 (=4 mod 32)
// so every mma fragment gather is bank-conflict-free.
// ---------------------------------------------------------------------------
#define QLD 132
#define VLD 136
#define SLD 68
#define ATT_SMEM_FLOATS (64*QLD + 64*VLD + 64*SLD + 192)
#define ATT_SMEM_BYTES  (ATT_SMEM_FLOATS * 4)

__global__ __launch_bounds__(256) void attn_mma_kernel(
    const float* __restrict__ qkv, float* __restrict__ attn)
{
    extern __shared__ float sm[];
    float* sQ     = sm;                 // [64][132]
    float* sKV    = sQ + 64 * QLD;      // [64][132] as K, [64][136] as V
    float* sS     = sKV + 64 * VLD;     // [64][68]
    float* sM     = sS + 64 * SLD;      // [64]
    float* sL     = sM + 64;            // [64]
    float* sAlpha = sL + 64;            // [64]

    int tid = threadIdx.x;
    int lane = tid & 31, w = tid >> 5;
    int wm = w & 3, wn = w >> 2;        // 4 x 2
    int g = lane >> 2, tc = lane & 3;
    int qt = (SS / 64 - 1) - blockIdx.x;   // reverse: big tiles first
    int h  = blockIdx.y, b = blockIdx.z;
    int kvh = h >> 2;
    int q0 = qt * 64;
    const float scale = 0.08838834764831845f;  // 1/sqrt(128)

    // load Q tile
    const float* qbase = qkv + ((size_t)(b * SS + q0)) * QKVD + h * HDD;
    #pragma unroll
    for (int e = 0; e < 8; e++) {
        int i = tid + e * 256;
        int r = i >> 5, c = (i & 31) << 2;
        float4 v = *(const float4*)(qbase + (size_t)r * QKVD + c);
        float* d = &sQ[r * QLD + c];
        d[0] = v.x; d[1] = v.y; d[2] = v.z; d[3] = v.w;
    }
    if (tid < 64) { sM[tid] = -1e30f; sL[tid] = 0.f; }

    float acc_o[8][4];
    #pragma unroll
    for (int nf = 0; nf < 8; nf++)
        #pragma unroll
        for (int r = 0; r < 4; r++) acc_o[nf][r] = 0.f;

    for (int kt = 0; kt <= qt; kt++) {
        int k0 = kt * 64;
        const float* kbase = qkv + ((size_t)(b * SS + k0)) * QKVD + QDIM + kvh * HDD;
        const float* vbase = kbase + KVDIM;

        __syncthreads();   // prev iter done with sKV(V)/sS; also covers Q/sM init

        // ---- load K ----
        #pragma unroll
        for (int e = 0; e < 8; e++) {
            int i = tid + e * 256;
            int r = i >> 5, c = (i & 31) << 2;
            float4 v = *(const float4*)(kbase + (size_t)r * QKVD + c);
            float* d = &sKV[r * QLD + c];
            d[0] = v.x; d[1] = v.y; d[2] = v.z; d[3] = v.w;
        }
        __syncthreads();

        // ---- S = Q K^T (tf32 mma) ----
        float sacc[4][4] = {};
        const float* Aq = sQ + (wm * 16 + g) * QLD;
        #pragma unroll
        for (int ks = 0; ks < 16; ks++) {
            unsigned a[4];
            const float* ap = Aq + ks * 8 + tc;
            a[0] = cvt_tf32(ap[0]);
            a[1] = cvt_tf32(ap[8 * QLD]);
            a[2] = cvt_tf32(ap[4]);
            a[3] = cvt_tf32(ap[8 * QLD + 4]);
            #pragma unroll
            for (int nf = 0; nf < 4; nf++) {
                const float* bp = sKV + (wn * 32 + nf * 8 + g) * QLD + ks * 8 + tc;
                unsigned bb[2] = { cvt_tf32(bp[0]), cvt_tf32(bp[4]) };
                mma_tf32(sacc[nf], a, bb);
            }
        }

        // ---- scale + causal mask, write S to smem ----
        {
            bool diag = (kt == qt);
            int srow = wm * 16 + g;
            #pragma unroll
            for (int nf = 0; nf < 4; nf++) {
                int col = wn * 32 + nf * 8 + 2 * tc;
                float v0 = sacc[nf][0] * scale, v1 = sacc[nf][1] * scale;
                float v2 = sacc[nf][2] * scale, v3 = sacc[nf][3] * scale;
                if (diag) {
                    int qr = q0 + srow, kc = k0 + col;
                    if (kc     > qr)     v0 = -1e30f;
                    if (kc + 1 > qr)     v1 = -1e30f;
                    if (kc     > qr + 8) v2 = -1e30f;
                    if (kc + 1 > qr + 8) v3 = -1e30f;
                }
                *(float2*)(&sS[srow * SLD + col])       = make_float2(v0, v1);
                *(float2*)(&sS[(srow + 8) * SLD + col]) = make_float2(v2, v3);
            }
        }
        __syncthreads();   // S complete; K consumed

        // ---- load V (reuse sKV, stride VLD) ----
        #pragma unroll
        for (int e = 0; e < 8; e++) {
            int i = tid + e * 256;
            int r = i >> 5, c = (i & 31) << 2;
            float4 v = *(const float4*)(vbase + (size_t)r * QKVD + c);
            float* d = &sKV[r * VLD + c];
            d[0] = v.x; d[1] = v.y; d[2] = v.z; d[3] = v.w;
        }

        // ---- online softmax: 4 threads per row ----
        {
            int row = tid >> 2, sub = tid & 3;
            float* sr = sS + row * SLD + sub * 16;
            float mx = -1e30f;
            #pragma unroll
            for (int k2 = 0; k2 < 16; k2++) mx = fmaxf(mx, sr[k2]);
            mx = fmaxf(mx, __shfl_xor_sync(0xffffffffu, mx, 1));
            mx = fmaxf(mx, __shfl_xor_sync(0xffffffffu, mx, 2));
            float mold = sM[row];
            float mnew = fmaxf(mold, mx);
            float sumv = 0.f;
            #pragma unroll
            for (int k2 = 0; k2 < 16; k2++) {
                float p = __expf(sr[k2] - mnew);
                sr[k2] = p;
                sumv += p;
            }
            sumv += __shfl_xor_sync(0xffffffffu, sumv, 1);
            sumv += __shfl_xor_sync(0xffffffffu, sumv, 2);
            if (sub == 0) {
                float alpha = __expf(mold - mnew);
                sAlpha[row] = alpha;
                sM[row] = mnew;
                sL[row] = sL[row] * alpha + sumv;
            }
        }
        __syncthreads();   // P + V + alpha ready

        // ---- O = O*alpha + P V (tf32 mma) ----
        float al0 = sAlpha[wm * 16 + g];
        float al1 = sAlpha[wm * 16 + g + 8];
        #pragma unroll
        for (int nf = 0; nf < 8; nf++) {
            acc_o[nf][0] *= al0; acc_o[nf][1] *= al0;
            acc_o[nf][2] *= al1; acc_o[nf][3] *= al1;
        }
        const float* Ap = sS + (wm * 16 + g) * SLD;
        #pragma unroll
        for (int ks = 0; ks < 8; ks++) {
            unsigned a[4];
            const float* ap = Ap + ks * 8 + tc;
            a[0] = cvt_tf32(ap[0]);
            a[1] = cvt_tf32(ap[8 * SLD]);
            a[2] = cvt_tf32(ap[4]);
            a[3] = cvt_tf32(ap[8 * SLD + 4]);
            #pragma unroll
            for (int nf = 0; nf < 8; nf++) {
                const float* bp = sKV + (ks * 8 + tc) * VLD + wn * 64 + nf * 8 + g;
                unsigned bb[2] = { cvt_tf32(bp[0]), cvt_tf32(bp[4 * VLD]) };
                mma_tf32(acc_o[nf], a, bb);
            }
        }
    }

    // ---- epilogue ----
    float inv0 = 1.f / sL[wm * 16 + g];
    float inv1 = 1.f / sL[wm * 16 + g + 8];
    int row = q0 + wm * 16 + g;
    float* ob = attn + ((size_t)(b * SS + row)) * QDIM + h * HDD + wn * 64;
    #pragma unroll
    for (int nf = 0; nf < 8; nf++) {
        *(float2*)(ob + nf * 8 + 2 * tc) =
            make_float2(acc_o[nf][0] * inv0, acc_o[nf][1] * inv0);
        *(float2*)(ob + (size_t)8 * QDIM + nf * 8 + 2 * tc) =
            make_float2(acc_o[nf][2] * inv1, acc_o[nf][3] * inv1);
    }
}

// ---------------------------------------------------------------------------
extern "C" void kernel_launch(void* const* d_in, const int* in_sizes, int n_in,
                              void* d_out, int out_size)
{
    (void)in_sizes; (void)n_in; (void)out_size;
    const float* x     = (const float*)d_in[0];
    const float* freqs = (const float*)d_in[1];
    const float* Wqkv  = (const float*)d_in[2];
    const float* Wo    = (const float*)d_in[3];
    float* out = (float*)d_out;

    float *qkvp, *attnp;
    cudaGetSymbolAddress((void**)&qkvp, g_qkv);
    cudaGetSymbolAddress((void**)&attnp, g_attn);
    cudaFuncSetAttribute(attn_mma_kernel, cudaFuncAttributeMaxDynamicSharedMemorySize,
                         ATT_SMEM_BYTES);
    cudaFuncSetAttribute(gemm_bf16x3_nt, cudaFuncAttributeMaxDynamicSharedMemorySize,
                         GEMM_SMEM_BYTES);

    // 1) QKV projection
    gemm_bf16x3_nt<<<dim3(QKVD / TBN, MROWS / TBM), 256, GEMM_SMEM_BYTES>>>(
        x, Wqkv, qkvp, MROWS, QKVD, DD);

    // 2) RoPE
    rope_kernel<<<(BB * SS * 20 * 64) / 256, 256>>>(qkvp, freqs);

    // 3) causal GQA flash attention (tf32 tensor cores)
    attn_mma_kernel<<<dim3(SS / 64, NHH, BB), 256, ATT_SMEM_BYTES>>>(qkvp, attnp);

    // 4) output projection
    gemm_bf16x3_nt<<<dim3(DD / TBN, MROWS / TBM), 256, GEMM_SMEM_BYTES>>>(
        attnp, Wo, out, MROWS, DD, QDIM);
}

// round 4
// speedup vs baseline: 2.9490x; 1.1259x over previous
#include <cuda_runtime.h>

#define BB 2
#define SS 2048
#define DD 2048
#define NHH 16
#define NKVV 4
#define HDD 128
#define QDIM 2048
#define KVDIM 512
#define QKVD 3072
#define MROWS (BB*SS)   // 4096

// fp32 scratch
__device__ float g_qkv[(size_t)MROWS * QKVD];   // [B*S, 3072]
__device__ float g_attn[(size_t)MROWS * QDIM];  // [B*S, 2048]

// packed bf16 hi/lo planes (one u32 = 2 adjacent-k bf16)
__device__ unsigned g_xh[(size_t)MROWS * DD / 2],   g_xl[(size_t)MROWS * DD / 2];
__device__ unsigned g_wqh[(size_t)QKVD * DD / 2],   g_wql[(size_t)QKVD * DD / 2];
__device__ unsigned g_ah[(size_t)MROWS * QDIM / 2], g_al[(size_t)MROWS * QDIM / 2];
__device__ unsigned g_woh[(size_t)DD * QDIM / 2],   g_wol[(size_t)DD * QDIM / 2];

// ---------------------------------------------------------------------------
// MMA helpers
// ---------------------------------------------------------------------------
__device__ __forceinline__ unsigned cvt_tf32(float x) {
    unsigned r;
    asm("cvt.rna.tf32.f32 %0, %1;" : "=r"(r) : "f"(x));
    return r;
}
__device__ __forceinline__ float cvt_tf32f(float x) {
    return __uint_as_float(cvt_tf32(x));
}

__device__ __forceinline__ void mma_tf32(float* c, const unsigned* a, const unsigned* b) {
    asm volatile(
        "mma.sync.aligned.m16n8k8.row.col.f32.tf32.tf32.f32 "
        "{%0,%1,%2,%3},{%4,%5,%6,%7},{%8,%9},{%0,%1,%2,%3};"
        : "+f"(c[0]), "+f"(c[1]), "+f"(c[2]), "+f"(c[3])
        : "r"(a[0]), "r"(a[1]), "r"(a[2]), "r"(a[3]), "r"(b[0]), "r"(b[1]));
}

__device__ __forceinline__ void mma_bf16(float* c, const unsigned* a, const unsigned* b) {
    asm volatile(
        "mma.sync.aligned.m16n8k16.row.col.f32.bf16.bf16.f32 "
        "{%0,%1,%2,%3},{%4,%5,%6,%7},{%8,%9},{%0,%1,%2,%3};"
        : "+f"(c[0]), "+f"(c[1]), "+f"(c[2]), "+f"(c[3])
        : "r"(a[0]), "r"(a[1]), "r"(a[2]), "r"(a[3]), "r"(b[0]), "r"(b[1]));
}

// ---------------------------------------------------------------------------
// Split fp32 -> packed bf16 hi/lo planes. word i = elements (2i, 2i+1),
// element 2i in the low half (little-endian smem/mma convention).
// ---------------------------------------------------------------------------
__global__ __launch_bounds__(256) void split_kernel(
    const float4* __restrict__ in, uint2* __restrict__ hi, uint2* __restrict__ lo,
    int n4)
{
    int i = blockIdx.x * blockDim.x + threadIdx.x;
    if (i >= n4) return;
    float4 v = in[i];
    unsigned b0 = __float_as_uint(v.x), b1 = __float_as_uint(v.y);
    unsigned b2 = __float_as_uint(v.z), b3 = __float_as_uint(v.w);
    uint2 h, l;
    asm("prmt.b32 %0, %1, %2, 0x7632;" : "=r"(h.x) : "r"(b0), "r"(b1));
    asm("prmt.b32 %0, %1, %2, 0x7632;" : "=r"(h.y) : "r"(b2), "r"(b3));
    float l0 = v.x - __uint_as_float(b0 & 0xffff0000u);
    float l1 = v.y - __uint_as_float(b1 & 0xffff0000u);
    float l2 = v.z - __uint_as_float(b2 & 0xffff0000u);
    float l3 = v.w - __uint_as_float(b3 & 0xffff0000u);
    asm("cvt.rn.satfinite.bf16x2.f32 %0, %1, %2;" : "=r"(l.x) : "f"(l1), "f"(l0));
    asm("cvt.rn.satfinite.bf16x2.f32 %0, %1, %2;" : "=r"(l.y) : "f"(l3), "f"(l2));
    hi[i] = h;
    lo[i] = l;
}

// ---------------------------------------------------------------------------
// Pure-bf16 x3 NT GEMM on pre-split planes: C = A*B^T (~fp32 accuracy).
// 128x128 tile, BK=32 elems (16 words), 256 threads (2x4 warps), 64x32/warp.
// smem row stride 20 words -> all fragment gathers bank-conflict-free.
// ---------------------------------------------------------------------------
#define PLANE_W (128 * 20)            // words per plane per stage
#define STAGE_W (4 * PLANE_W)         // Ah, Al, Bh, Bl
#define GEMM_SMEM_BYTES (2 * STAGE_W * 4)   // 81920

__global__ __launch_bounds__(256, 2) void gemm_planes_nt(
    const unsigned* __restrict__ Ah, const unsigned* __restrict__ Al,
    const unsigned* __restrict__ Bh, const unsigned* __restrict__ Bl,
    float* __restrict__ C, int M, int N, int K)
{
    extern __shared__ unsigned usm[];
    const int KW = K >> 1;

    int tid = threadIdx.x;
    int lane = tid & 31, w = tid >> 5;
    int wm = w >> 2, wn = w & 3;
    int g = lane >> 2, tc = lane & 3;
    int m0 = blockIdx.y * 128, n0 = blockIdx.x * 128;

    int lr = tid >> 2;            // 0..63
    int lw = (tid & 3) * 4;       // word offset 0,4,8,12

    const unsigned* gp[4] = {
        Ah + (size_t)(m0 + lr) * KW + lw,
        Al + (size_t)(m0 + lr) * KW + lw,
        Bh + (size_t)(n0 + lr) * KW + lw,
        Bl + (size_t)(n0 + lr) * KW + lw };

    float acc[4][4][4] = {};

    auto load_stage = [&](int t, int buf) {
        unsigned* st = usm + buf * STAGE_W;
        size_t ko = (size_t)t * 16;
        #pragma unroll
        for (int p = 0; p < 4; p++) {
            #pragma unroll
            for (int r2 = 0; r2 < 2; r2++) {
                unsigned* d = st + p * PLANE_W + (lr + r2 * 64) * 20 + lw;
                unsigned da = (unsigned)__cvta_generic_to_shared(d);
                asm volatile("cp.async.ca.shared.global [%0], [%1], 16;\n"
                             :: "r"(da), "l"(gp[p] + (size_t)r2 * 64 * KW + ko));
            }
        }
        asm volatile("cp.async.commit_group;\n");
    };

    int T = K / 32;
    load_stage(0, 0);

    for (int t = 0; t < T; t++) {
        asm volatile("cp.async.wait_group 0;\n");
        __syncthreads();
        if (t + 1 < T) load_stage(t + 1, (t + 1) & 1);

        const unsigned* st = usm + (t & 1) * STAGE_W;
        const unsigned* cAh = st + 0 * PLANE_W + (wm * 64) * 20;
        const unsigned* cAl = st + 1 * PLANE_W + (wm * 64) * 20;
        const unsigned* cBh = st + 2 * PLANE_W + (wn * 32) * 20;
        const unsigned* cBl = st + 3 * PLANE_W + (wn * 32) * 20;

        #pragma unroll
        for (int ks = 0; ks < 2; ks++) {
            unsigned ah[4][4], al[4][4];
            #pragma unroll
            for (int mf = 0; mf < 4; mf++) {
                int ba = (mf * 16 + g) * 20 + ks * 8 + tc;
                ah[mf][0] = cAh[ba];       ah[mf][1] = cAh[ba + 160];
                ah[mf][2] = cAh[ba + 4];   ah[mf][3] = cAh[ba + 164];
                al[mf][0] = cAl[ba];       al[mf][1] = cAl[ba + 160];
                al[mf][2] = cAl[ba + 4];   al[mf][3] = cAl[ba + 164];
            }
            #pragma unroll
            for (int nf = 0; nf < 4; nf++) {
                int bb = (nf * 8 + g) * 20 + ks * 8 + tc;
                unsigned bh[2] = { cBh[bb], cBh[bb + 4] };
                unsigned bl[2] = { cBl[bb], cBl[bb + 4] };
                #pragma unroll
                for (int mf = 0; mf < 4; mf++) {
                    mma_bf16(acc[mf][nf], ah[mf], bh);
                    mma_bf16(acc[mf][nf], ah[mf], bl);
                    mma_bf16(acc[mf][nf], al[mf], bh);
                }
            }
        }
        __syncthreads();
    }

    #pragma unroll
    for (int mf = 0; mf < 4; mf++) {
        #pragma unroll
        for (int nf = 0; nf < 4; nf++) {
            int row = m0 + wm * 64 + mf * 16 + g;
            int col = n0 + wn * 32 + nf * 8 + 2 * tc;
            *(float2*)(C + (size_t)row * N + col) =
                make_float2(acc[mf][nf][0], acc[mf][nf][1]);
            *(float2*)(C + (size_t)(row + 8) * N + col) =
                make_float2(acc[mf][nf][2], acc[mf][nf][3]);
        }
    }
}

// ---------------------------------------------------------------------------
// RoPE (in-place on g_qkv)
// ---------------------------------------------------------------------------
__global__ __launch_bounds__(256) void rope_kernel(
    float* __restrict__ qkv, const float* __restrict__ freqs)
{
    int idx = blockIdx.x * blockDim.x + threadIdx.x;
    int i    = idx & 63;
    int head = (idx >> 6) % 20;
    int bs   = idx / (64 * 20);
    int s    = bs & (SS - 1);

    int off = (head < NHH) ? head * HDD : QDIM + (head - NHH) * HDD;
    size_t base = (size_t)bs * QKVD + off + 2 * i;

    float t0 = qkv[base], t1 = qkv[base + 1];
    float f0 = freqs[s * HDD + 2 * i];
    float f1 = freqs[s * HDD + 2 * i + 1];
    qkv[base]     = t0 * f1 - t1 * f0;
    qkv[base + 1] = t0 * f0 + t1 * f1;
}

// ---------------------------------------------------------------------------
// Causal flash attention, TF32 tensor cores, GQA kvh=h>>2.
// Operands pre-converted to TF32 at smem-store time (zero cvt in mma loops).
// ---------------------------------------------------------------------------
#define QLD 132
#define VLD 136
#define SLD 68
#define ATT_SMEM_FLOATS (64*QLD + 64*VLD + 64*SLD + 192)
#define ATT_SMEM_BYTES  (ATT_SMEM_FLOATS * 4)

__global__ __launch_bounds__(256) void attn_mma_kernel(
    const float* __restrict__ qkv, float* __restrict__ attn)
{
    extern __shared__ float sm[];
    float* sQ     = sm;                 // [64][132] (tf32)
    float* sKV    = sQ + 64 * QLD;      // K: [64][132], V: [64][136] (tf32)
    float* sS     = sKV + 64 * VLD;     // [64][68]
    float* sM     = sS + 64 * SLD;
    float* sL     = sM + 64;
    float* sAlpha = sL + 64;

    int tid = threadIdx.x;
    int lane = tid & 31, w = tid >> 5;
    int wm = w & 3, wn = w >> 2;        // 4 x 2
    int g = lane >> 2, tc = lane & 3;
    int qt = (SS / 64 - 1) - blockIdx.x;
    int h  = blockIdx.y, b = blockIdx.z;
    int kvh = h >> 2;
    int q0 = qt * 64;
    const float scale = 0.08838834764831845f;

    const float* qbase = qkv + ((size_t)(b * SS + q0)) * QKVD + h * HDD;
    #pragma unroll
    for (int e = 0; e < 8; e++) {
        int i = tid + e * 256;
        int r = i >> 5, c = (i & 31) << 2;
        float4 v = *(const float4*)(qbase + (size_t)r * QKVD + c);
        float* d = &sQ[r * QLD + c];
        d[0] = cvt_tf32f(v.x); d[1] = cvt_tf32f(v.y);
        d[2] = cvt_tf32f(v.z); d[3] = cvt_tf32f(v.w);
    }
    if (tid < 64) { sM[tid] = -1e30f; sL[tid] = 0.f; }

    float acc_o[8][4];
    #pragma unroll
    for (int nf = 0; nf < 8; nf++)
        #pragma unroll
        for (int r = 0; r < 4; r++) acc_o[nf][r] = 0.f;

    for (int kt = 0; kt <= qt; kt++) {
        int k0 = kt * 64;
        const float* kbase = qkv + ((size_t)(b * SS + k0)) * QKVD + QDIM + kvh * HDD;
        const float* vbase = kbase + KVDIM;

        __syncthreads();

        // ---- load K (tf32) ----
        #pragma unroll
        for (int e = 0; e < 8; e++) {
            int i = tid + e * 256;
            int r = i >> 5, c = (i & 31) << 2;
            float4 v = *(const float4*)(kbase + (size_t)r * QKVD + c);
            float* d = &sKV[r * QLD + c];
            d[0] = cvt_tf32f(v.x); d[1] = cvt_tf32f(v.y);
            d[2] = cvt_tf32f(v.z); d[3] = cvt_tf32f(v.w);
        }
        __syncthreads();

        // ---- S = Q K^T ----
        float sacc[4][4] = {};
        const float* Aq = sQ + (wm * 16 + g) * QLD;
        #pragma unroll
        for (int ks = 0; ks < 16; ks++) {
            unsigned a[4];
            const unsigned* ap = (const unsigned*)(Aq + ks * 8 + tc);
            a[0] = ap[0];
            a[1] = ap[8 * QLD];
            a[2] = ap[4];
            a[3] = ap[8 * QLD + 4];
            #pragma unroll
            for (int nf = 0; nf < 4; nf++) {
                const unsigned* bp = (const unsigned*)(sKV + (wn * 32 + nf * 8 + g) * QLD + ks * 8 + tc);
                unsigned bb[2] = { bp[0], bp[4] };
                mma_tf32(sacc[nf], a, bb);
            }
        }

        // ---- scale + causal mask ----
        {
            bool diag = (kt == qt);
            int srow = wm * 16 + g;
            #pragma unroll
            for (int nf = 0; nf < 4; nf++) {
                int col = wn * 32 + nf * 8 + 2 * tc;
                float v0 = sacc[nf][0] * scale, v1 = sacc[nf][1] * scale;
                float v2 = sacc[nf][2] * scale, v3 = sacc[nf][3] * scale;
                if (diag) {
                    int qr = q0 + srow, kc = k0 + col;
                    if (kc     > qr)     v0 = -1e30f;
                    if (kc + 1 > qr)     v1 = -1e30f;
                    if (kc     > qr + 8) v2 = -1e30f;
                    if (kc + 1 > qr + 8) v3 = -1e30f;
                }
                *(float2*)(&sS[srow * SLD + col])       = make_float2(v0, v1);
                *(float2*)(&sS[(srow + 8) * SLD + col]) = make_float2(v2, v3);
            }
        }
        __syncthreads();

        // ---- load V (tf32, stride VLD) ----
        #pragma unroll
        for (int e = 0; e < 8; e++) {
            int i = tid + e * 256;
            int r = i >> 5, c = (i & 31) << 2;
            float4 v = *(const float4*)(vbase + (size_t)r * QKVD + c);
            float* d = &sKV[r * VLD + c];
            d[0] = cvt_tf32f(v.x); d[1] = cvt_tf32f(v.y);
            d[2] = cvt_tf32f(v.z); d[3] = cvt_tf32f(v.w);
        }

        // ---- online softmax (4 threads/row); P stored pre-converted ----
        {
            int row = tid >> 2, sub = tid & 3;
            float* sr = sS + row * SLD + sub * 16;
            float mx = -1e30f;
            #pragma unroll
            for (int k2 = 0; k2 < 16; k2++) mx = fmaxf(mx, sr[k2]);
            mx = fmaxf(mx, __shfl_xor_sync(0xffffffffu, mx, 1));
            mx = fmaxf(mx, __shfl_xor_sync(0xffffffffu, mx, 2));
            float mold = sM[row];
            float mnew = fmaxf(mold, mx);
            float sumv = 0.f;
            #pragma unroll
            for (int k2 = 0; k2 < 16; k2++) {
                float p = __expf(sr[k2] - mnew);
                sr[k2] = cvt_tf32f(p);
                sumv += p;
            }
            sumv += __shfl_xor_sync(0xffffffffu, sumv, 1);
            sumv += __shfl_xor_sync(0xffffffffu, sumv, 2);
            if (sub == 0) {
                float alpha = __expf(mold - mnew);
                sAlpha[row] = alpha;
                sM[row] = mnew;
                sL[row] = sL[row] * alpha + sumv;
            }
        }
        __syncthreads();

        // ---- O = O*alpha + P V ----
        float al0 = sAlpha[wm * 16 + g];
        float al1 = sAlpha[wm * 16 + g + 8];
        #pragma unroll
        for (int nf = 0; nf < 8; nf++) {
            acc_o[nf][0] *= al0; acc_o[nf][1] *= al0;
            acc_o[nf][2] *= al1; acc_o[nf][3] *= al1;
        }
        const float* Ap = sS + (wm * 16 + g) * SLD;
        #pragma unroll
        for (int ks = 0; ks < 8; ks++) {
            unsigned a[4];
            const unsigned* ap = (const unsigned*)(Ap + ks * 8 + tc);
            a[0] = ap[0];
            a[1] = ap[8 * SLD];
            a[2] = ap[4];
            a[3] = ap[8 * SLD + 4];
            #pragma unroll
            for (int nf = 0; nf < 8; nf++) {
                const unsigned* bp = (const unsigned*)(sKV + (ks * 8 + tc) * VLD + wn * 64 + nf * 8 + g);
                unsigned bb[2] = { bp[0], bp[4 * VLD] };
                mma_tf32(acc_o[nf], a, bb);
            }
        }
    }

    // ---- epilogue ----
    float inv0 = 1.f / sL[wm * 16 + g];
    float inv1 = 1.f / sL[wm * 16 + g + 8];
    int row = q0 + wm * 16 + g;
    float* ob = attn + ((size_t)(b * SS + row)) * QDIM + h * HDD + wn * 64;
    #pragma unroll
    for (int nf = 0; nf < 8; nf++) {
        *(float2*)(ob + nf * 8 + 2 * tc) =
            make_float2(acc_o[nf][0] * inv0, acc_o[nf][1] * inv0);
        *(float2*)(ob + (size_t)8 * QDIM + nf * 8 + 2 * tc) =
            make_float2(acc_o[nf][2] * inv1, acc_o[nf][3] * inv1);
    }
}

// ---------------------------------------------------------------------------
extern "C" void kernel_launch(void* const* d_in, const int* in_sizes, int n_in,
                              void* d_out, int out_size)
{
    (void)in_sizes; (void)n_in; (void)out_size;
    const float* x     = (const float*)d_in[0];
    const float* freqs = (const float*)d_in[1];
    const float* Wqkv  = (const float*)d_in[2];
    const float* Wo    = (const float*)d_in[3];
    float* out = (float*)d_out;

    float *qkvp, *attnp;
    unsigned *xh, *xl, *wqh, *wql, *ah, *al, *woh, *wol;
    cudaGetSymbolAddress((void**)&qkvp, g_qkv);
    cudaGetSymbolAddress((void**)&attnp, g_attn);
    cudaGetSymbolAddress((void**)&xh, g_xh);   cudaGetSymbolAddress((void**)&xl, g_xl);
    cudaGetSymbolAddress((void**)&wqh, g_wqh); cudaGetSymbolAddress((void**)&wql, g_wql);
    cudaGetSymbolAddress((void**)&ah, g_ah);   cudaGetSymbolAddress((void**)&al, g_al);
    cudaGetSymbolAddress((void**)&woh, g_woh); cudaGetSymbolAddress((void**)&wol, g_wol);

    cudaFuncSetAttribute(attn_mma_kernel, cudaFuncAttributeMaxDynamicSharedMemorySize,
                         ATT_SMEM_BYTES);
    cudaFuncSetAttribute(gemm_planes_nt, cudaFuncAttributeMaxDynamicSharedMemorySize,
                         GEMM_SMEM_BYTES);

    // 0) split inputs into bf16 hi/lo planes
    {
        int n4;
        n4 = MROWS * DD / 4;
        split_kernel<<<n4 / 256, 256>>>((const float4*)x, (uint2*)xh, (uint2*)xl, n4);
        n4 = QKVD * DD / 4;
        split_kernel<<<n4 / 256, 256>>>((const float4*)Wqkv, (uint2*)wqh, (uint2*)wql, n4);
        n4 = DD * QDIM / 4;
        split_kernel<<<n4 / 256, 256>>>((const float4*)Wo, (uint2*)woh, (uint2*)wol, n4);
    }

    // 1) QKV projection: [4096,3072] = x @ Wqkv^T  (bf16x3)
    gemm_planes_nt<<<dim3(QKVD / 128, MROWS / 128), 256, GEMM_SMEM_BYTES>>>(
        xh, xl, wqh, wql, qkvp, MROWS, QKVD, DD);

    // 2) RoPE
    rope_kernel<<<(BB * SS * 20 * 64) / 256, 256>>>(qkvp, freqs);

    // 3) causal GQA flash attention (tf32)
    attn_mma_kernel<<<dim3(SS / 64, NHH, BB), 256, ATT_SMEM_BYTES>>>(qkvp, attnp);

    // 3b) split attention output
    {
        int n4 = MROWS * QDIM / 4;
        split_kernel<<<n4 / 256, 256>>>((const float4*)attnp, (uint2*)ah, (uint2*)al, n4);
    }

    // 4) output projection: out = attn @ Wo^T  (bf16x3)
    gemm_planes_nt<<<dim3(DD / 128, MROWS / 128), 256, GEMM_SMEM_BYTES>>>(
        ah, al, woh, wol, out, MROWS, DD, QDIM);
}

// round 5
// speedup vs baseline: 3.0283x; 1.0269x over previous
#include <cuda_runtime.h>

#define BB 2
#define SS 2048
#define DD 2048
#define NHH 16
#define NKVV 4
#define HDD 128
#define QDIM 2048
#define KVDIM 512
#define QKVD 3072
#define MROWS (BB*SS)   // 4096

// fp32 scratch
__device__ float g_qkv[(size_t)MROWS * QKVD];   // [B*S, 3072]
__device__ float g_attn[(size_t)MROWS * QDIM];  // [B*S, 2048]

// packed bf16 hi/lo planes
__device__ unsigned g_xh[(size_t)MROWS * DD / 2],   g_xl[(size_t)MROWS * DD / 2];
__device__ unsigned g_wqh[(size_t)QKVD * DD / 2],   g_wql[(size_t)QKVD * DD / 2];
__device__ unsigned g_ah[(size_t)MROWS * QDIM / 2], g_al[(size_t)MROWS * QDIM / 2];
__device__ unsigned g_woh[(size_t)DD * QDIM / 2],   g_wol[(size_t)DD * QDIM / 2];

// ---------------------------------------------------------------------------
// helpers
// ---------------------------------------------------------------------------
__device__ __forceinline__ unsigned cvt_tf32(float x) {
    unsigned r;
    asm("cvt.rna.tf32.f32 %0, %1;" : "=r"(r) : "f"(x));
    return r;
}
__device__ __forceinline__ float cvt_tf32f(float x) {
    return __uint_as_float(cvt_tf32(x));
}

__device__ __forceinline__ void mma_tf32(float* c, const unsigned* a, const unsigned* b) {
    asm volatile(
        "mma.sync.aligned.m16n8k8.row.col.f32.tf32.tf32.f32 "
        "{%0,%1,%2,%3},{%4,%5,%6,%7},{%8,%9},{%0,%1,%2,%3};"
        : "+f"(c[0]), "+f"(c[1]), "+f"(c[2]), "+f"(c[3])
        : "r"(a[0]), "r"(a[1]), "r"(a[2]), "r"(a[3]), "r"(b[0]), "r"(b[1]));
}

__device__ __forceinline__ void mma_bf16(float* c, const unsigned* a, const unsigned* b) {
    asm volatile(
        "mma.sync.aligned.m16n8k16.row.col.f32.bf16.bf16.f32 "
        "{%0,%1,%2,%3},{%4,%5,%6,%7},{%8,%9},{%0,%1,%2,%3};"
        : "+f"(c[0]), "+f"(c[1]), "+f"(c[2]), "+f"(c[3])
        : "r"(a[0]), "r"(a[1]), "r"(a[2]), "r"(a[3]), "r"(b[0]), "r"(b[1]));
}

__device__ __forceinline__ void cp16(void* smem_dst, const void* gsrc) {
    unsigned d = (unsigned)__cvta_generic_to_shared(smem_dst);
    asm volatile("cp.async.ca.shared.global [%0], [%1], 16;\n" :: "r"(d), "l"(gsrc));
}

// ---------------------------------------------------------------------------
// Split fp32 -> packed bf16 hi/lo planes
// ---------------------------------------------------------------------------
__global__ __launch_bounds__(256) void split_kernel(
    const float4* __restrict__ in, uint2* __restrict__ hi, uint2* __restrict__ lo,
    int n4)
{
    int i = blockIdx.x * blockDim.x + threadIdx.x;
    if (i >= n4) return;
    float4 v = in[i];
    unsigned b0 = __float_as_uint(v.x), b1 = __float_as_uint(v.y);
    unsigned b2 = __float_as_uint(v.z), b3 = __float_as_uint(v.w);
    uint2 h, l;
    asm("prmt.b32 %0, %1, %2, 0x7632;" : "=r"(h.x) : "r"(b0), "r"(b1));
    asm("prmt.b32 %0, %1, %2, 0x7632;" : "=r"(h.y) : "r"(b2), "r"(b3));
    float l0 = v.x - __uint_as_float(b0 & 0xffff0000u);
    float l1 = v.y - __uint_as_float(b1 & 0xffff0000u);
    float l2 = v.z - __uint_as_float(b2 & 0xffff0000u);
    float l3 = v.w - __uint_as_float(b3 & 0xffff0000u);
    asm("cvt.rn.satfinite.bf16x2.f32 %0, %1, %2;" : "=r"(l.x) : "f"(l1), "f"(l0));
    asm("cvt.rn.satfinite.bf16x2.f32 %0, %1, %2;" : "=r"(l.y) : "f"(l3), "f"(l2));
    hi[i] = h;
    lo[i] = l;
}

// ---------------------------------------------------------------------------
// Pure-bf16 x3 NT GEMM on pre-split planes (unchanged from R4)
// ---------------------------------------------------------------------------
#define PLANE_W (128 * 20)
#define STAGE_W (4 * PLANE_W)
#define GEMM_SMEM_BYTES (2 * STAGE_W * 4)

__global__ __launch_bounds__(256, 2) void gemm_planes_nt(
    const unsigned* __restrict__ Ah, const unsigned* __restrict__ Al,
    const unsigned* __restrict__ Bh, const unsigned* __restrict__ Bl,
    float* __restrict__ C, int M, int N, int K)
{
    extern __shared__ unsigned usm[];
    const int KW = K >> 1;

    int tid = threadIdx.x;
    int lane = tid & 31, w = tid >> 5;
    int wm = w >> 2, wn = w & 3;
    int g = lane >> 2, tc = lane & 3;
    int m0 = blockIdx.y * 128, n0 = blockIdx.x * 128;

    int lr = tid >> 2;
    int lw = (tid & 3) * 4;

    const unsigned* gp[4] = {
        Ah + (size_t)(m0 + lr) * KW + lw,
        Al + (size_t)(m0 + lr) * KW + lw,
        Bh + (size_t)(n0 + lr) * KW + lw,
        Bl + (size_t)(n0 + lr) * KW + lw };

    float acc[4][4][4] = {};

    auto load_stage = [&](int t, int buf) {
        unsigned* st = usm + buf * STAGE_W;
        size_t ko = (size_t)t * 16;
        #pragma unroll
        for (int p = 0; p < 4; p++) {
            #pragma unroll
            for (int r2 = 0; r2 < 2; r2++) {
                unsigned* d = st + p * PLANE_W + (lr + r2 * 64) * 20 + lw;
                unsigned da = (unsigned)__cvta_generic_to_shared(d);
                asm volatile("cp.async.ca.shared.global [%0], [%1], 16;\n"
                             :: "r"(da), "l"(gp[p] + (size_t)r2 * 64 * KW + ko));
            }
        }
        asm volatile("cp.async.commit_group;\n");
    };

    int T = K / 32;
    load_stage(0, 0);

    for (int t = 0; t < T; t++) {
        asm volatile("cp.async.wait_group 0;\n");
        __syncthreads();
        if (t + 1 < T) load_stage(t + 1, (t + 1) & 1);

        const unsigned* st = usm + (t & 1) * STAGE_W;
        const unsigned* cAh = st + 0 * PLANE_W + (wm * 64) * 20;
        const unsigned* cAl = st + 1 * PLANE_W + (wm * 64) * 20;
        const unsigned* cBh = st + 2 * PLANE_W + (wn * 32) * 20;
        const unsigned* cBl = st + 3 * PLANE_W + (wn * 32) * 20;

        #pragma unroll
        for (int ks = 0; ks < 2; ks++) {
            unsigned ah[4][4], al[4][4];
            #pragma unroll
            for (int mf = 0; mf < 4; mf++) {
                int ba = (mf * 16 + g) * 20 + ks * 8 + tc;
                ah[mf][0] = cAh[ba];       ah[mf][1] = cAh[ba + 160];
                ah[mf][2] = cAh[ba + 4];   ah[mf][3] = cAh[ba + 164];
                al[mf][0] = cAl[ba];       al[mf][1] = cAl[ba + 160];
                al[mf][2] = cAl[ba + 4];   al[mf][3] = cAl[ba + 164];
            }
            #pragma unroll
            for (int nf = 0; nf < 4; nf++) {
                int bb = (nf * 8 + g) * 20 + ks * 8 + tc;
                unsigned bh[2] = { cBh[bb], cBh[bb + 4] };
                unsigned bl[2] = { cBl[bb], cBl[bb + 4] };
                #pragma unroll
                for (int mf = 0; mf < 4; mf++) {
                    mma_bf16(acc[mf][nf], ah[mf], bh);
                    mma_bf16(acc[mf][nf], ah[mf], bl);
                    mma_bf16(acc[mf][nf], al[mf], bh);
                }
            }
        }
        __syncthreads();
    }

    #pragma unroll
    for (int mf = 0; mf < 4; mf++) {
        #pragma unroll
        for (int nf = 0; nf < 4; nf++) {
            int row = m0 + wm * 64 + mf * 16 + g;
            int col = n0 + wn * 32 + nf * 8 + 2 * tc;
            *(float2*)(C + (size_t)row * N + col) =
                make_float2(acc[mf][nf][0], acc[mf][nf][1]);
            *(float2*)(C + (size_t)(row + 8) * N + col) =
                make_float2(acc[mf][nf][2], acc[mf][nf][3]);
        }
    }
}

// ---------------------------------------------------------------------------
// RoPE + tf32 pre-rounding of q,k,v in place.
// heads 0..15: q (rotate), 16..19: k (rotate), 20..23: v (round only).
// ---------------------------------------------------------------------------
__global__ __launch_bounds__(256) void rope_kernel(
    float* __restrict__ qkv, const float* __restrict__ freqs)
{
    int idx = blockIdx.x * blockDim.x + threadIdx.x;
    int i    = idx & 63;
    int head = (idx >> 6) % 24;
    int bs   = idx / (64 * 24);
    int s    = bs & (SS - 1);

    if (head < 20) {
        int off = (head < NHH) ? head * HDD : QDIM + (head - NHH) * HDD;
        size_t base = (size_t)bs * QKVD + off + 2 * i;
        float t0 = qkv[base], t1 = qkv[base + 1];
        float f0 = freqs[s * HDD + 2 * i];
        float f1 = freqs[s * HDD + 2 * i + 1];
        qkv[base]     = cvt_tf32f(t0 * f1 - t1 * f0);
        qkv[base + 1] = cvt_tf32f(t0 * f0 + t1 * f1);
    } else {
        size_t base = (size_t)bs * QKVD + QDIM + KVDIM + (head - 20) * HDD + 2 * i;
        qkv[base]     = cvt_tf32f(qkv[base]);
        qkv[base + 1] = cvt_tf32f(qkv[base + 1]);
    }
}

// ---------------------------------------------------------------------------
// Causal flash attention, TF32 mma, cp.async-pipelined. GQA kvh=h>>2.
// 128 q-rows per CTA, 64 k-cols per iteration, HD=128.
// 8 warps x 16 rows. Operands pre-rounded to tf32 in gmem -> raw cp.async.
// Commit pattern [Q+K0][V0][K1][V1]... ; wait_group 1 before S (K ready,
// overlapped with softmax+PV) and before PV (V ready, overlapped with S).
// ---------------------------------------------------------------------------
#define QLD 132
#define KLD 132
#define VLD 136
#define SLD 68
#define ATT_SMEM_FLOATS (128*QLD + 64*KLD + 64*VLD + 128*SLD + 3*128)
#define ATT_SMEM_BYTES  (ATT_SMEM_FLOATS * 4)   // 172544

__global__ __launch_bounds__(256, 1) void attn_mma_kernel(
    const float* __restrict__ qkv, float* __restrict__ attn)
{
    extern __shared__ float sm[];
    float* sQ  = sm;                   // [128][132]
    float* sK  = sQ + 128 * QLD;       // [64][132]
    float* sV  = sK + 64 * KLD;        // [64][136]
    float* sS  = sV + 64 * VLD;        // [128][68]
    float* sMx = sS + 128 * SLD;       // [128]
    float* sLs = sMx + 128;            // [128]
    float* sAl = sLs + 128;            // [128]

    int tid = threadIdx.x;
    int lane = tid & 31, w = tid >> 5;     // warp = row-block 0..7
    int g = lane >> 2, tc = lane & 3;
    int qt = (SS / 128 - 1) - blockIdx.x;  // reverse: heavy tiles first
    int h  = blockIdx.y, b = blockIdx.z;
    int kvh = h >> 2;
    int q0 = qt * 128;
    const float scale = 0.08838834764831845f;

    const float* kvbase = qkv + (size_t)b * SS * QKVD + QDIM + kvh * HDD;

    auto issueK = [&](int kt) {
        const float* src = kvbase + (size_t)kt * 64 * QKVD;
        #pragma unroll
        for (int e = 0; e < 8; e++) {
            int i = tid + e * 256;
            int r = i >> 5, c = (i & 31) << 2;
            cp16(sK + r * KLD + c, src + (size_t)r * QKVD + c);
        }
        asm volatile("cp.async.commit_group;\n");
    };
    auto issueV = [&](int kt) {
        const float* src = kvbase + KVDIM + (size_t)kt * 64 * QKVD;
        #pragma unroll
        for (int e = 0; e < 8; e++) {
            int i = tid + e * 256;
            int r = i >> 5, c = (i & 31) << 2;
            cp16(sV + r * VLD + c, src + (size_t)r * QKVD + c);
        }
        asm volatile("cp.async.commit_group;\n");
    };

    // prologue: Q + K0 in one group, then V0
    {
        const float* qbase = qkv + ((size_t)(b * SS + q0)) * QKVD + h * HDD;
        #pragma unroll
        for (int e = 0; e < 16; e++) {
            int i = tid + e * 256;
            int r = i >> 5, c = (i & 31) << 2;
            cp16(sQ + r * QLD + c, qbase + (size_t)r * QKVD + c);
        }
        const float* src = kvbase;
        #pragma unroll
        for (int e = 0; e < 8; e++) {
            int i = tid + e * 256;
            int r = i >> 5, c = (i & 31) << 2;
            cp16(sK + r * KLD + c, src + (size_t)r * QKVD + c);
        }
        asm volatile("cp.async.commit_group;\n");
        issueV(0);
    }
    if (tid < 128) { sMx[tid] = -1e30f; sLs[tid] = 0.f; }

    float acc[16][4];
    #pragma unroll
    for (int nf = 0; nf < 16; nf++)
        #pragma unroll
        for (int r = 0; r < 4; r++) acc[nf][r] = 0.f;

    int ktmax = 2 * qt + 1;
    for (int kt = 0; kt <= ktmax; kt++) {
        // ---- wait K[kt] (leaves V[kt] pending) ----
        asm volatile("cp.async.wait_group 1;\n");
        __syncthreads();

        // ---- S = Q K^T ----
        float sacc[8][4] = {};
        const float* Aq = sQ + (w * 16 + g) * QLD;
        #pragma unroll
        for (int ks = 0; ks < 16; ks++) {
            const unsigned* ap = (const unsigned*)(Aq + ks * 8 + tc);
            unsigned a[4] = { ap[0], ap[8 * QLD], ap[4], ap[8 * QLD + 4] };
            #pragma unroll
            for (int nf = 0; nf < 8; nf++) {
                const unsigned* bp = (const unsigned*)(sK + (nf * 8 + g) * KLD + ks * 8 + tc);
                unsigned bb[2] = { bp[0], bp[4] };
                mma_tf32(sacc[nf], a, bb);
            }
        }

        // ---- scale + causal mask + store S ----
        {
            int k0 = kt * 64;
            bool diag = (kt >= 2 * qt);
            int srow = w * 16 + g;
            #pragma unroll
            for (int nf = 0; nf < 8; nf++) {
                int col = nf * 8 + 2 * tc;
                float v0 = sacc[nf][0] * scale, v1 = sacc[nf][1] * scale;
                float v2 = sacc[nf][2] * scale, v3 = sacc[nf][3] * scale;
                if (diag) {
                    int qr = q0 + srow, kc = k0 + col;
                    if (kc     > qr)     v0 = -1e30f;
                    if (kc + 1 > qr)     v1 = -1e30f;
                    if (kc     > qr + 8) v2 = -1e30f;
                    if (kc + 1 > qr + 8) v3 = -1e30f;
                }
                *(float2*)(&sS[srow * SLD + col])       = make_float2(v0, v1);
                *(float2*)(&sS[(srow + 8) * SLD + col]) = make_float2(v2, v3);
            }
        }
        __syncthreads();            // S complete, sK consumed

        if (kt + 1 <= ktmax) issueK(kt + 1);   // overlaps softmax + PV

        // ---- online softmax (2 threads/row, 32 cols each) ----
        {
            int row = tid >> 1, sub = tid & 1;
            float* sr = sS + row * SLD + sub * 32;
            float mx = -1e30f;
            #pragma unroll 8
            for (int k2 = 0; k2 < 32; k2++) mx = fmaxf(mx, sr[k2]);
            mx = fmaxf(mx, __shfl_xor_sync(0xffffffffu, mx, 1));
            float mold = sMx[row];
            float mnew = fmaxf(mold, mx);
            float sumv = 0.f;
            #pragma unroll 8
            for (int k2 = 0; k2 < 32; k2++) {
                float p = __expf(sr[k2] - mnew);
                sr[k2] = cvt_tf32f(p);
                sumv += p;
            }
            sumv += __shfl_xor_sync(0xffffffffu, sumv, 1);
            if (sub == 0) {
                float alpha = __expf(mold - mnew);
                sAl[row] = alpha;
                sMx[row] = mnew;
                sLs[row] = sLs[row] * alpha + sumv;
            }
        }

        // ---- wait V[kt] ----
        if (kt < ktmax) asm volatile("cp.async.wait_group 1;\n");
        else            asm volatile("cp.async.wait_group 0;\n");
        __syncthreads();            // softmax done, V visible

        // ---- O = O*alpha + P V ----
        float al0 = sAl[w * 16 + g];
        float al1 = sAl[w * 16 + g + 8];
        #pragma unroll
        for (int nf = 0; nf < 16; nf++) {
            acc[nf][0] *= al0; acc[nf][1] *= al0;
            acc[nf][2] *= al1; acc[nf][3] *= al1;
        }
        const float* Ap = sS + (w * 16 + g) * SLD;
        #pragma unroll
        for (int ks = 0; ks < 8; ks++) {
            const unsigned* ap = (const unsigned*)(Ap + ks * 8 + tc);
            unsigned a[4] = { ap[0], ap[8 * SLD], ap[4], ap[8 * SLD + 4] };
            #pragma unroll
            for (int nf = 0; nf < 16; nf++) {
                const unsigned* bp = (const unsigned*)(sV + (ks * 8 + tc) * VLD + nf * 8 + g);
                unsigned bb[2] = { bp[0], bp[4 * VLD] };
                mma_tf32(acc[nf], a, bb);
            }
        }
        __syncthreads();            // PV done: sV, sS free

        if (kt + 1 <= ktmax) issueV(kt + 1);   // overlaps next S
    }

    // ---- epilogue ----
    float inv0 = 1.f / sLs[w * 16 + g];
    float inv1 = 1.f / sLs[w * 16 + g + 8];
    int row = q0 + w * 16 + g;
    float* ob = attn + ((size_t)(b * SS + row)) * QDIM + h * HDD;
    #pragma unroll
    for (int nf = 0; nf < 16; nf++) {
        *(float2*)(ob + nf * 8 + 2 * tc) =
            make_float2(acc[nf][0] * inv0, acc[nf][1] * inv0);
        *(float2*)(ob + (size_t)8 * QDIM + nf * 8 + 2 * tc) =
            make_float2(acc[nf][2] * inv1, acc[nf][3] * inv1);
    }
}

// ---------------------------------------------------------------------------
extern "C" void kernel_launch(void* const* d_in, const int* in_sizes, int n_in,
                              void* d_out, int out_size)
{
    (void)in_sizes; (void)n_in; (void)out_size;
    const float* x     = (const float*)d_in[0];
    const float* freqs = (const float*)d_in[1];
    const float* Wqkv  = (const float*)d_in[2];
    const float* Wo    = (const float*)d_in[3];
    float* out = (float*)d_out;

    float *qkvp, *attnp;
    unsigned *xh, *xl, *wqh, *wql, *ah, *al, *woh, *wol;
    cudaGetSymbolAddress((void**)&qkvp, g_qkv);
    cudaGetSymbolAddress((void**)&attnp, g_attn);
    cudaGetSymbolAddress((void**)&xh, g_xh);   cudaGetSymbolAddress((void**)&xl, g_xl);
    cudaGetSymbolAddress((void**)&wqh, g_wqh); cudaGetSymbolAddress((void**)&wql, g_wql);
    cudaGetSymbolAddress((void**)&ah, g_ah);   cudaGetSymbolAddress((void**)&al, g_al);
    cudaGetSymbolAddress((void**)&woh, g_woh); cudaGetSymbolAddress((void**)&wol, g_wol);

    cudaFuncSetAttribute(attn_mma_kernel, cudaFuncAttributeMaxDynamicSharedMemorySize,
                         ATT_SMEM_BYTES);
    cudaFuncSetAttribute(gemm_planes_nt, cudaFuncAttributeMaxDynamicSharedMemorySize,
                         GEMM_SMEM_BYTES);

    // 0) split inputs into bf16 hi/lo planes
    {
        int n4;
        n4 = MROWS * DD / 4;
        split_kernel<<<n4 / 256, 256>>>((const float4*)x, (uint2*)xh, (uint2*)xl, n4);
        n4 = QKVD * DD / 4;
        split_kernel<<<n4 / 256, 256>>>((const float4*)Wqkv, (uint2*)wqh, (uint2*)wql, n4);
        n4 = DD * QDIM / 4;
        split_kernel<<<n4 / 256, 256>>>((const float4*)Wo, (uint2*)woh, (uint2*)wol, n4);
    }

    // 1) QKV projection (bf16x3)
    gemm_planes_nt<<<dim3(QKVD / 128, MROWS / 128), 256, GEMM_SMEM_BYTES>>>(
        xh, xl, wqh, wql, qkvp, MROWS, QKVD, DD);

    // 2) RoPE + tf32 pre-round (q,k rotated; v rounded)
    rope_kernel<<<(BB * SS * 24 * 64) / 256, 256>>>(qkvp, freqs);

    // 3) causal GQA flash attention (tf32, cp.async pipelined)
    attn_mma_kernel<<<dim3(SS / 128, NHH, BB), 256, ATT_SMEM_BYTES>>>(qkvp, attnp);

    // 3b) split attention output
    {
        int n4 = MROWS * QDIM / 4;
        split_kernel<<<n4 / 256, 256>>>((const float4*)attnp, (uint2*)ah, (uint2*)al, n4);
    }

    // 4) output projection (bf16x3)
    gemm_planes_nt<<<dim3(DD / 128, MROWS / 128), 256, GEMM_SMEM_BYTES>>>(
        ah, al, woh, wol, out, MROWS, DD, QDIM);
}

// round 6
// speedup vs baseline: 3.0926x; 1.0212x over previous
#include <cuda_runtime.h>

#define BB 2
#define SS 2048
#define DD 2048
#define NHH 16
#define NKVV 4
#define HDD 128
#define QDIM 2048
#define KVDIM 512
#define QKVD 3072
#define MROWS (BB*SS)   // 4096

// fp32 scratch
__device__ float g_qkv[(size_t)MROWS * QKVD];
__device__ float g_attn[(size_t)MROWS * QDIM];

// packed bf16 hi/lo planes
__device__ unsigned g_xh[(size_t)MROWS * DD / 2],   g_xl[(size_t)MROWS * DD / 2];
__device__ unsigned g_wqh[(size_t)QKVD * DD / 2],   g_wql[(size_t)QKVD * DD / 2];
__device__ unsigned g_ah[(size_t)MROWS * QDIM / 2], g_al[(size_t)MROWS * QDIM / 2];
__device__ unsigned g_woh[(size_t)DD * QDIM / 2],   g_wol[(size_t)DD * QDIM / 2];

// ---------------------------------------------------------------------------
// helpers
// ---------------------------------------------------------------------------
__device__ __forceinline__ unsigned cvt_tf32(float x) {
    unsigned r;
    asm("cvt.rna.tf32.f32 %0, %1;" : "=r"(r) : "f"(x));
    return r;
}
__device__ __forceinline__ float cvt_tf32f(float x) {
    return __uint_as_float(cvt_tf32(x));
}

__device__ __forceinline__ void mma_tf32(float* c, const unsigned* a, const unsigned* b) {
    asm volatile(
        "mma.sync.aligned.m16n8k8.row.col.f32.tf32.tf32.f32 "
        "{%0,%1,%2,%3},{%4,%5,%6,%7},{%8,%9},{%0,%1,%2,%3};"
        : "+f"(c[0]), "+f"(c[1]), "+f"(c[2]), "+f"(c[3])
        : "r"(a[0]), "r"(a[1]), "r"(a[2]), "r"(a[3]), "r"(b[0]), "r"(b[1]));
}

__device__ __forceinline__ void mma_bf16(float* c, const unsigned* a, const unsigned* b) {
    asm volatile(
        "mma.sync.aligned.m16n8k16.row.col.f32.bf16.bf16.f32 "
        "{%0,%1,%2,%3},{%4,%5,%6,%7},{%8,%9},{%0,%1,%2,%3};"
        : "+f"(c[0]), "+f"(c[1]), "+f"(c[2]), "+f"(c[3])
        : "r"(a[0]), "r"(a[1]), "r"(a[2]), "r"(a[3]), "r"(b[0]), "r"(b[1]));
}

__device__ __forceinline__ void cp16(void* smem_dst, const void* gsrc) {
    unsigned d = (unsigned)__cvta_generic_to_shared(smem_dst);
    asm volatile("cp.async.ca.shared.global [%0], [%1], 16;\n" :: "r"(d), "l"(gsrc));
}

// ---------------------------------------------------------------------------
// Split fp32 -> packed bf16 hi/lo planes
// ---------------------------------------------------------------------------
__global__ __launch_bounds__(256) void split_kernel(
    const float4* __restrict__ in, uint2* __restrict__ hi, uint2* __restrict__ lo,
    int n4)
{
    int i = blockIdx.x * blockDim.x + threadIdx.x;
    if (i >= n4) return;
    float4 v = in[i];
    unsigned b0 = __float_as_uint(v.x), b1 = __float_as_uint(v.y);
    unsigned b2 = __float_as_uint(v.z), b3 = __float_as_uint(v.w);
    uint2 h, l;
    asm("prmt.b32 %0, %1, %2, 0x7632;" : "=r"(h.x) : "r"(b0), "r"(b1));
    asm("prmt.b32 %0, %1, %2, 0x7632;" : "=r"(h.y) : "r"(b2), "r"(b3));
    float l0 = v.x - __uint_as_float(b0 & 0xffff0000u);
    float l1 = v.y - __uint_as_float(b1 & 0xffff0000u);
    float l2 = v.z - __uint_as_float(b2 & 0xffff0000u);
    float l3 = v.w - __uint_as_float(b3 & 0xffff0000u);
    asm("cvt.rn.satfinite.bf16x2.f32 %0, %1, %2;" : "=r"(l.x) : "f"(l1), "f"(l0));
    asm("cvt.rn.satfinite.bf16x2.f32 %0, %1, %2;" : "=r"(l.y) : "f"(l3), "f"(l2));
    hi[i] = h;
    lo[i] = l;
}

// ---------------------------------------------------------------------------
// Pure-bf16 x3 NT GEMM on pre-split planes (unchanged)
// ---------------------------------------------------------------------------
#define PLANE_W (128 * 20)
#define STAGE_W (4 * PLANE_W)
#define GEMM_SMEM_BYTES (2 * STAGE_W * 4)

__global__ __launch_bounds__(256, 2) void gemm_planes_nt(
    const unsigned* __restrict__ Ah, const unsigned* __restrict__ Al,
    const unsigned* __restrict__ Bh, const unsigned* __restrict__ Bl,
    float* __restrict__ C, int M, int N, int K)
{
    extern __shared__ unsigned usm[];
    const int KW = K >> 1;

    int tid = threadIdx.x;
    int lane = tid & 31, w = tid >> 5;
    int wm = w >> 2, wn = w & 3;
    int g = lane >> 2, tc = lane & 3;
    int m0 = blockIdx.y * 128, n0 = blockIdx.x * 128;

    int lr = tid >> 2;
    int lw = (tid & 3) * 4;

    const unsigned* gp[4] = {
        Ah + (size_t)(m0 + lr) * KW + lw,
        Al + (size_t)(m0 + lr) * KW + lw,
        Bh + (size_t)(n0 + lr) * KW + lw,
        Bl + (size_t)(n0 + lr) * KW + lw };

    float acc[4][4][4] = {};

    auto load_stage = [&](int t, int buf) {
        unsigned* st = usm + buf * STAGE_W;
        size_t ko = (size_t)t * 16;
        #pragma unroll
        for (int p = 0; p < 4; p++) {
            #pragma unroll
            for (int r2 = 0; r2 < 2; r2++) {
                unsigned* d = st + p * PLANE_W + (lr + r2 * 64) * 20 + lw;
                unsigned da = (unsigned)__cvta_generic_to_shared(d);
                asm volatile("cp.async.ca.shared.global [%0], [%1], 16;\n"
                             :: "r"(da), "l"(gp[p] + (size_t)r2 * 64 * KW + ko));
            }
        }
        asm volatile("cp.async.commit_group;\n");
    };

    int T = K / 32;
    load_stage(0, 0);

    for (int t = 0; t < T; t++) {
        asm volatile("cp.async.wait_group 0;\n");
        __syncthreads();
        if (t + 1 < T) load_stage(t + 1, (t + 1) & 1);

        const unsigned* st = usm + (t & 1) * STAGE_W;
        const unsigned* cAh = st + 0 * PLANE_W + (wm * 64) * 20;
        const unsigned* cAl = st + 1 * PLANE_W + (wm * 64) * 20;
        const unsigned* cBh = st + 2 * PLANE_W + (wn * 32) * 20;
        const unsigned* cBl = st + 3 * PLANE_W + (wn * 32) * 20;

        #pragma unroll
        for (int ks = 0; ks < 2; ks++) {
            unsigned ah[4][4], al[4][4];
            #pragma unroll
            for (int mf = 0; mf < 4; mf++) {
                int ba = (mf * 16 + g) * 20 + ks * 8 + tc;
                ah[mf][0] = cAh[ba];       ah[mf][1] = cAh[ba + 160];
                ah[mf][2] = cAh[ba + 4];   ah[mf][3] = cAh[ba + 164];
                al[mf][0] = cAl[ba];       al[mf][1] = cAl[ba + 160];
                al[mf][2] = cAl[ba + 4];   al[mf][3] = cAl[ba + 164];
            }
            #pragma unroll
            for (int nf = 0; nf < 4; nf++) {
                int bb = (nf * 8 + g) * 20 + ks * 8 + tc;
                unsigned bh[2] = { cBh[bb], cBh[bb + 4] };
                unsigned bl[2] = { cBl[bb], cBl[bb + 4] };
                #pragma unroll
                for (int mf = 0; mf < 4; mf++) {
                    mma_bf16(acc[mf][nf], ah[mf], bh);
                    mma_bf16(acc[mf][nf], ah[mf], bl);
                    mma_bf16(acc[mf][nf], al[mf], bh);
                }
            }
        }
        __syncthreads();
    }

    #pragma unroll
    for (int mf = 0; mf < 4; mf++) {
        #pragma unroll
        for (int nf = 0; nf < 4; nf++) {
            int row = m0 + wm * 64 + mf * 16 + g;
            int col = n0 + wn * 32 + nf * 8 + 2 * tc;
            *(float2*)(C + (size_t)row * N + col) =
                make_float2(acc[mf][nf][0], acc[mf][nf][1]);
            *(float2*)(C + (size_t)(row + 8) * N + col) =
                make_float2(acc[mf][nf][2], acc[mf][nf][3]);
        }
    }
}

// ---------------------------------------------------------------------------
// RoPE + tf32 pre-rounding of q,k,v in place.
// ---------------------------------------------------------------------------
__global__ __launch_bounds__(256) void rope_kernel(
    float* __restrict__ qkv, const float* __restrict__ freqs)
{
    int idx = blockIdx.x * blockDim.x + threadIdx.x;
    int i    = idx & 63;
    int head = (idx >> 6) % 24;
    int bs   = idx / (64 * 24);
    int s    = bs & (SS - 1);

    if (head < 20) {
        int off = (head < NHH) ? head * HDD : QDIM + (head - NHH) * HDD;
        size_t base = (size_t)bs * QKVD + off + 2 * i;
        float t0 = qkv[base], t1 = qkv[base + 1];
        float f0 = freqs[s * HDD + 2 * i];
        float f1 = freqs[s * HDD + 2 * i + 1];
        qkv[base]     = cvt_tf32f(t0 * f1 - t1 * f0);
        qkv[base + 1] = cvt_tf32f(t0 * f0 + t1 * f1);
    } else {
        size_t base = (size_t)bs * QKVD + QDIM + KVDIM + (head - 20) * HDD + 2 * i;
        qkv[base]     = cvt_tf32f(qkv[base]);
        qkv[base + 1] = cvt_tf32f(qkv[base + 1]);
    }
}

// ---------------------------------------------------------------------------
// Causal flash attention, TF32 mma, FA2-style register softmax.
// 128 q-rows/CTA, 64 k-cols/iter. 8 warps; warp w owns rows w*16..w*16+15
// for S, softmax, P, PV (warp-private -> no barrier between S and PV).
// K double-buffered, V single-buffered via cp.async.
// Commit order/iter: [V_kt][K_{kt+1}] ; wait_group 2 before S (K_kt ready),
// wait_group 1 before PV (V_kt ready).
// ---------------------------------------------------------------------------
#define QLD 132
#define KLD 132
#define VLD 136
#define SLD 68
#define ATT_SMEM_FLOATS (128*QLD + 2*64*KLD + 64*VLD + 128*SLD)
#define ATT_SMEM_BYTES  (ATT_SMEM_FLOATS * 4)   // 204800

__global__ __launch_bounds__(256, 1) void attn_mma_kernel(
    const float* __restrict__ qkv, float* __restrict__ attn)
{
    extern __shared__ float sm[];
    float* sQ = sm;                    // [128][132]
    float* sK = sQ + 128 * QLD;        // [2][64][132]
    float* sV = sK + 2 * 64 * KLD;     // [64][136]
    float* sP = sV + 64 * VLD;         // [128][68]

    int tid = threadIdx.x;
    int lane = tid & 31, w = tid >> 5;
    int g = lane >> 2, tc = lane & 3;
    int qt = (SS / 128 - 1) - blockIdx.x;   // heavy tiles first
    int h  = blockIdx.y, b = blockIdx.z;
    int kvh = h >> 2;
    int q0 = qt * 128;
    int ktmax = 2 * qt + 1;
    const float scale = 0.08838834764831845f;

    const float* kvbase = qkv + (size_t)b * SS * QKVD + QDIM + kvh * HDD;

    auto issueK = [&](int kt) {
        if (kt <= ktmax) {
            float* dst = sK + (kt & 1) * 64 * KLD;
            const float* src = kvbase + (size_t)kt * 64 * QKVD;
            #pragma unroll
            for (int e = 0; e < 8; e++) {
                int i = tid + e * 256;
                int r = i >> 5, c = (i & 31) << 2;
                cp16(dst + r * KLD + c, src + (size_t)r * QKVD + c);
            }
        }
        asm volatile("cp.async.commit_group;\n");
    };
    auto issueV = [&](int kt) {
        const float* src = kvbase + KVDIM + (size_t)kt * 64 * QKVD;
        #pragma unroll
        for (int e = 0; e < 8; e++) {
            int i = tid + e * 256;
            int r = i >> 5, c = (i & 31) << 2;
            cp16(sV + r * VLD + c, src + (size_t)r * QKVD + c);
        }
        asm volatile("cp.async.commit_group;\n");
    };

    // prologue: [Q + K0] as one group
    {
        const float* qbase = qkv + ((size_t)(b * SS + q0)) * QKVD + h * HDD;
        #pragma unroll
        for (int e = 0; e < 16; e++) {
            int i = tid + e * 256;
            int r = i >> 5, c = (i & 31) << 2;
            cp16(sQ + r * QLD + c, qbase + (size_t)r * QKVD + c);
        }
        const float* src = kvbase;
        #pragma unroll
        for (int e = 0; e < 8; e++) {
            int i = tid + e * 256;
            int r = i >> 5, c = (i & 31) << 2;
            cp16(sK + r * KLD + c, src + (size_t)r * QKVD + c);
        }
        asm volatile("cp.async.commit_group;\n");
    }

    float m0r = -1e30f, m1r = -1e30f, l0r = 0.f, l1r = 0.f;
    float acc[16][4];
    #pragma unroll
    for (int nf = 0; nf < 16; nf++)
        #pragma unroll
        for (int r = 0; r < 4; r++) acc[nf][r] = 0.f;

    int srow = w * 16 + g;

    for (int kt = 0; kt <= ktmax; kt++) {
        __syncthreads();                 // A: all warps done iter kt-1 (sV, sK[(kt+1)&1] free)
        issueV(kt);
        issueK(kt + 1);

        asm volatile("cp.async.wait_group 2;\n");   // K[kt] ready
        __syncthreads();                 // B: K visible to all

        // ---- S = Q K^T ----
        const float* sKb = sK + (kt & 1) * 64 * KLD;
        float sacc[8][4] = {};
        const float* Aq = sQ + srow * QLD;
        #pragma unroll
        for (int ks = 0; ks < 16; ks++) {
            const unsigned* ap = (const unsigned*)(Aq + ks * 8 + tc);
            unsigned a[4] = { ap[0], ap[8 * QLD], ap[4], ap[8 * QLD + 4] };
            #pragma unroll
            for (int nf = 0; nf < 8; nf++) {
                const unsigned* bp = (const unsigned*)(sKb + (nf * 8 + g) * KLD + ks * 8 + tc);
                unsigned bb[2] = { bp[0], bp[4] };
                mma_tf32(sacc[nf], a, bb);
            }
        }

        // ---- scale + mask (registers) ----
        {
            int k0 = kt * 64;
            bool diag = (kt >= 2 * qt);
            #pragma unroll
            for (int nf = 0; nf < 8; nf++) {
                float v0 = sacc[nf][0] * scale, v1 = sacc[nf][1] * scale;
                float v2 = sacc[nf][2] * scale, v3 = sacc[nf][3] * scale;
                if (diag) {
                    int qr = q0 + srow, kc = k0 + nf * 8 + 2 * tc;
                    if (kc     > qr)     v0 = -1e30f;
                    if (kc + 1 > qr)     v1 = -1e30f;
                    if (kc     > qr + 8) v2 = -1e30f;
                    if (kc + 1 > qr + 8) v3 = -1e30f;
                }
                sacc[nf][0] = v0; sacc[nf][1] = v1;
                sacc[nf][2] = v2; sacc[nf][3] = v3;
            }
        }

        // ---- register softmax (rows srow, srow+8; reduce over tc lanes) ----
        float alpha0, alpha1;
        {
            float mx0 = -1e30f, mx1 = -1e30f;
            #pragma unroll
            for (int nf = 0; nf < 8; nf++) {
                mx0 = fmaxf(mx0, fmaxf(sacc[nf][0], sacc[nf][1]));
                mx1 = fmaxf(mx1, fmaxf(sacc[nf][2], sacc[nf][3]));
            }
            mx0 = fmaxf(mx0, __shfl_xor_sync(0xffffffffu, mx0, 1));
            mx0 = fmaxf(mx0, __shfl_xor_sync(0xffffffffu, mx0, 2));
            mx1 = fmaxf(mx1, __shfl_xor_sync(0xffffffffu, mx1, 1));
            mx1 = fmaxf(mx1, __shfl_xor_sync(0xffffffffu, mx1, 2));

            float mn0 = fmaxf(m0r, mx0), mn1 = fmaxf(m1r, mx1);
            alpha0 = __expf(m0r - mn0);
            alpha1 = __expf(m1r - mn1);

            float s0 = 0.f, s1 = 0.f;
            #pragma unroll
            for (int nf = 0; nf < 8; nf++) {
                float p0 = __expf(sacc[nf][0] - mn0);
                float p1 = __expf(sacc[nf][1] - mn0);
                float p2 = __expf(sacc[nf][2] - mn1);
                float p3 = __expf(sacc[nf][3] - mn1);
                s0 += p0 + p1;
                s1 += p2 + p3;
                int col = nf * 8 + 2 * tc;
                *(float2*)(&sP[srow * SLD + col]) =
                    make_float2(cvt_tf32f(p0), cvt_tf32f(p1));
                *(float2*)(&sP[(srow + 8) * SLD + col]) =
                    make_float2(cvt_tf32f(p2), cvt_tf32f(p3));
            }
            s0 += __shfl_xor_sync(0xffffffffu, s0, 1);
            s0 += __shfl_xor_sync(0xffffffffu, s0, 2);
            s1 += __shfl_xor_sync(0xffffffffu, s1, 1);
            s1 += __shfl_xor_sync(0xffffffffu, s1, 2);
            l0r = l0r * alpha0 + s0;
            l1r = l1r * alpha1 + s1;
            m0r = mn0; m1r = mn1;
        }
        __syncwarp();                    // P (warp-private) visible within warp

        // ---- rescale O ----
        #pragma unroll
        for (int nf = 0; nf < 16; nf++) {
            acc[nf][0] *= alpha0; acc[nf][1] *= alpha0;
            acc[nf][2] *= alpha1; acc[nf][3] *= alpha1;
        }

        asm volatile("cp.async.wait_group 1;\n");   // V[kt] ready
        __syncthreads();                 // C: V visible; all warps past S (sK safe)

        // ---- O += P V ----
        const float* Ap = sP + srow * SLD;
        #pragma unroll
        for (int ks = 0; ks < 8; ks++) {
            const unsigned* ap = (const unsigned*)(Ap + ks * 8 + tc);
            unsigned a[4] = { ap[0], ap[8 * SLD], ap[4], ap[8 * SLD + 4] };
            #pragma unroll
            for (int nf = 0; nf < 16; nf++) {
                const unsigned* bp = (const unsigned*)(sV + (ks * 8 + tc) * VLD + nf * 8 + g);
                unsigned bb[2] = { bp[0], bp[4 * VLD] };
                mma_tf32(acc[nf], a, bb);
            }
        }
    }

    // ---- epilogue (l in registers, replicated across tc) ----
    float inv0 = 1.f / l0r;
    float inv1 = 1.f / l1r;
    int row = q0 + srow;
    float* ob = attn + ((size_t)(b * SS + row)) * QDIM + h * HDD;
    #pragma unroll
    for (int nf = 0; nf < 16; nf++) {
        *(float2*)(ob + nf * 8 + 2 * tc) =
            make_float2(acc[nf][0] * inv0, acc[nf][1] * inv0);
        *(float2*)(ob + (size_t)8 * QDIM + nf * 8 + 2 * tc) =
            make_float2(acc[nf][2] * inv1, acc[nf][3] * inv1);
    }
}

// ---------------------------------------------------------------------------
extern "C" void kernel_launch(void* const* d_in, const int* in_sizes, int n_in,
                              void* d_out, int out_size)
{
    (void)in_sizes; (void)n_in; (void)out_size;
    const float* x     = (const float*)d_in[0];
    const float* freqs = (const float*)d_in[1];
    const float* Wqkv  = (const float*)d_in[2];
    const float* Wo    = (const float*)d_in[3];
    float* out = (float*)d_out;

    float *qkvp, *attnp;
    unsigned *xh, *xl, *wqh, *wql, *ah, *al, *woh, *wol;
    cudaGetSymbolAddress((void**)&qkvp, g_qkv);
    cudaGetSymbolAddress((void**)&attnp, g_attn);
    cudaGetSymbolAddress((void**)&xh, g_xh);   cudaGetSymbolAddress((void**)&xl, g_xl);
    cudaGetSymbolAddress((void**)&wqh, g_wqh); cudaGetSymbolAddress((void**)&wql, g_wql);
    cudaGetSymbolAddress((void**)&ah, g_ah);   cudaGetSymbolAddress((void**)&al, g_al);
    cudaGetSymbolAddress((void**)&woh, g_woh); cudaGetSymbolAddress((void**)&wol, g_wol);

    cudaFuncSetAttribute(attn_mma_kernel, cudaFuncAttributeMaxDynamicSharedMemorySize,
                         ATT_SMEM_BYTES);
    cudaFuncSetAttribute(gemm_planes_nt, cudaFuncAttributeMaxDynamicSharedMemorySize,
                         GEMM_SMEM_BYTES);

    // 0) split inputs into bf16 hi/lo planes
    {
        int n4;
        n4 = MROWS * DD / 4;
        split_kernel<<<n4 / 256, 256>>>((const float4*)x, (uint2*)xh, (uint2*)xl, n4);
        n4 = QKVD * DD / 4;
        split_kernel<<<n4 / 256, 256>>>((const float4*)Wqkv, (uint2*)wqh, (uint2*)wql, n4);
        n4 = DD * QDIM / 4;
        split_kernel<<<n4 / 256, 256>>>((const float4*)Wo, (uint2*)woh, (uint2*)wol, n4);
    }

    // 1) QKV projection (bf16x3)
    gemm_planes_nt<<<dim3(QKVD / 128, MROWS / 128), 256, GEMM_SMEM_BYTES>>>(
        xh, xl, wqh, wql, qkvp, MROWS, QKVD, DD);

    // 2) RoPE + tf32 pre-round
    rope_kernel<<<(BB * SS * 24 * 64) / 256, 256>>>(qkvp, freqs);

    // 3) causal GQA flash attention (tf32, register softmax)
    attn_mma_kernel<<<dim3(SS / 128, NHH, BB), 256, ATT_SMEM_BYTES>>>(qkvp, attnp);

    // 3b) split attention output
    {
        int n4 = MROWS * QDIM / 4;
        split_kernel<<<n4 / 256, 256>>>((const float4*)attnp, (uint2*)ah, (uint2*)al, n4);
    }

    // 4) output projection (bf16x3)
    gemm_planes_nt<<<dim3(DD / 128, MROWS / 128), 256, GEMM_SMEM_BYTES>>>(
        ah, al, woh, wol, out, MROWS, DD, QDIM);
}

// round 8
// speedup vs baseline: 3.4654x; 1.1205x over previous
#include <cuda_runtime.h>

#define BB 2
#define SS 2048
#define DD 2048
#define NHH 16
#define NKVV 4
#define HDD 128
#define QDIM 2048
#define KVDIM 512
#define QKVD 3072
#define MROWS (BB*SS)   // 4096

// fp32 scratch
__device__ float g_qkv[(size_t)MROWS * QKVD];
__device__ float g_attn[(size_t)MROWS * QDIM];

// packed bf16 hi/lo planes (one u32 = 2 adjacent-k bf16, k-major)
__device__ unsigned g_xh[(size_t)MROWS * DD / 2],   g_xl[(size_t)MROWS * DD / 2];
__device__ unsigned g_wqh[(size_t)QKVD * DD / 2],   g_wql[(size_t)QKVD * DD / 2];
__device__ unsigned g_ah[(size_t)MROWS * QDIM / 2], g_al[(size_t)MROWS * QDIM / 2];
__device__ unsigned g_woh[(size_t)DD * QDIM / 2],   g_wol[(size_t)DD * QDIM / 2];

// ---------------------------------------------------------------------------
// helpers
// ---------------------------------------------------------------------------
__device__ __forceinline__ unsigned cvt_tf32(float x) {
    unsigned r;
    asm("cvt.rna.tf32.f32 %0, %1;" : "=r"(r) : "f"(x));
    return r;
}
__device__ __forceinline__ float cvt_tf32f(float x) {
    return __uint_as_float(cvt_tf32(x));
}

__device__ __forceinline__ void mma_tf32(float* c, const unsigned* a, const unsigned* b) {
    asm volatile(
        "mma.sync.aligned.m16n8k8.row.col.f32.tf32.tf32.f32 "
        "{%0,%1,%2,%3},{%4,%5,%6,%7},{%8,%9},{%0,%1,%2,%3};"
        : "+f"(c[0]), "+f"(c[1]), "+f"(c[2]), "+f"(c[3])
        : "r"(a[0]), "r"(a[1]), "r"(a[2]), "r"(a[3]), "r"(b[0]), "r"(b[1]));
}

__device__ __forceinline__ void mma_bf16(float* c, const unsigned* a, const unsigned* b) {
    asm volatile(
        "mma.sync.aligned.m16n8k16.row.col.f32.bf16.bf16.f32 "
        "{%0,%1,%2,%3},{%4,%5,%6,%7},{%8,%9},{%0,%1,%2,%3};"
        : "+f"(c[0]), "+f"(c[1]), "+f"(c[2]), "+f"(c[3])
        : "r"(a[0]), "r"(a[1]), "r"(a[2]), "r"(a[3]), "r"(b[0]), "r"(b[1]));
}

__device__ __forceinline__ void ldsm4(unsigned* r, unsigned addr) {
    asm volatile("ldmatrix.sync.aligned.m8n8.x4.shared.b16 {%0,%1,%2,%3}, [%4];"
                 : "=r"(r[0]), "=r"(r[1]), "=r"(r[2]), "=r"(r[3]) : "r"(addr));
}

__device__ __forceinline__ void cp16(void* smem_dst, const void* gsrc) {
    unsigned d = (unsigned)__cvta_generic_to_shared(smem_dst);
    asm volatile("cp.async.ca.shared.global [%0], [%1], 16;\n" :: "r"(d), "l"(gsrc));
}

__device__ __forceinline__ unsigned smem_u32(const void* p) {
    return (unsigned)__cvta_generic_to_shared(p);
}

// ---------------------------------------------------------------------------
// Split fp32 -> packed bf16 hi/lo planes
// ---------------------------------------------------------------------------
__global__ __launch_bounds__(256) void split_kernel(
    const float4* __restrict__ in, uint2* __restrict__ hi, uint2* __restrict__ lo,
    int n4)
{
    int i = blockIdx.x * blockDim.x + threadIdx.x;
    if (i >= n4) return;
    float4 v = in[i];
    unsigned b0 = __float_as_uint(v.x), b1 = __float_as_uint(v.y);
    unsigned b2 = __float_as_uint(v.z), b3 = __float_as_uint(v.w);
    uint2 h, l;
    asm("prmt.b32 %0, %1, %2, 0x7632;" : "=r"(h.x) : "r"(b0), "r"(b1));
    asm("prmt.b32 %0, %1, %2, 0x7632;" : "=r"(h.y) : "r"(b2), "r"(b3));
    float l0 = v.x - __uint_as_float(b0 & 0xffff0000u);
    float l1 = v.y - __uint_as_float(b1 & 0xffff0000u);
    float l2 = v.z - __uint_as_float(b2 & 0xffff0000u);
    float l3 = v.w - __uint_as_float(b3 & 0xffff0000u);
    asm("cvt.rn.satfinite.bf16x2.f32 %0, %1, %2;" : "=r"(l.x) : "f"(l1), "f"(l0));
    asm("cvt.rn.satfinite.bf16x2.f32 %0, %1, %2;" : "=r"(l.y) : "f"(l3), "f"(l2));
    hi[i] = h;
    lo[i] = l;
}

// ---------------------------------------------------------------------------
// Pure-bf16 x3 NT GEMM on pre-split planes, ldmatrix fragment loads.
// 128x128 tile, BK=32 elems (16 words), 256 threads (2x4 warps), 64x32/warp.
// smem row stride 20 words (80 B): LDSM phases conflict-free (r*80 mod 128
// is a permutation of the eight 16B slots).
// ---------------------------------------------------------------------------
#define PLANE_W (128 * 20)                  // words per plane per stage
#define STAGE_W (4 * PLANE_W)               // Ah, Al, Bh, Bl
#define GEMM_SMEM_BYTES (2 * STAGE_W * 4)   // 81920
#define PLANE_B (PLANE_W * 4)               // 10240 bytes
#define STAGE_B (STAGE_W * 4)               // 40960 bytes

__global__ __launch_bounds__(256, 2) void gemm_planes_nt(
    const unsigned* __restrict__ Ah, const unsigned* __restrict__ Al,
    const unsigned* __restrict__ Bh, const unsigned* __restrict__ Bl,
    float* __restrict__ C, int M, int N, int K)
{
    extern __shared__ unsigned usm[];
    const int KW = K >> 1;

    int tid = threadIdx.x;
    int lane = tid & 31, w = tid >> 5;
    int wm = w >> 2, wn = w & 3;
    int g = lane >> 2, tc = lane & 3;
    int m0 = blockIdx.y * 128, n0 = blockIdx.x * 128;

    int lr = tid >> 2;
    int lw = (tid & 3) * 4;

    const unsigned* gp[4] = {
        Ah + (size_t)(m0 + lr) * KW + lw,
        Al + (size_t)(m0 + lr) * KW + lw,
        Bh + (size_t)(n0 + lr) * KW + lw,
        Bl + (size_t)(n0 + lr) * KW + lw };

    float acc[4][4][4] = {};

    auto load_stage = [&](int t, int buf) {
        unsigned* st = usm + buf * STAGE_W;
        size_t ko = (size_t)t * 16;
        #pragma unroll
        for (int p = 0; p < 4; p++) {
            #pragma unroll
            for (int r2 = 0; r2 < 2; r2++) {
                unsigned* d = st + p * PLANE_W + (lr + r2 * 64) * 20 + lw;
                unsigned da = (unsigned)__cvta_generic_to_shared(d);
                asm volatile("cp.async.ca.shared.global [%0], [%1], 16;\n"
                             :: "r"(da), "l"(gp[p] + (size_t)r2 * 64 * KW + ko));
            }
        }
        asm volatile("cp.async.commit_group;\n");
    };

    // ldmatrix lane-address components
    unsigned smem_base = smem_u32(usm);
    int arow = lane & 15;                       // A: row within 16
    int akc  = (lane >> 4) & 1;                 // A: k-halfword block (+16B)
    int brow = (lane & 7) | (((lane >> 4) & 1) << 3);   // B: row within 16 (pair)
    int bkc  = (lane >> 3) & 1;                 // B: k-halfword block

    unsigned aH = smem_base + 0 * PLANE_B + (unsigned)((wm * 64 + arow) * 80 + akc * 16);
    unsigned aL = aH + PLANE_B;
    unsigned bH = smem_base + 2 * PLANE_B + (unsigned)((wn * 32 + brow) * 80 + bkc * 16);
    unsigned bL = bH + PLANE_B;

    int T = K / 32;
    load_stage(0, 0);

    for (int t = 0; t < T; t++) {
        asm volatile("cp.async.wait_group 0;\n");
        __syncthreads();
        if (t + 1 < T) load_stage(t + 1, (t + 1) & 1);

        unsigned stg = (t & 1) * STAGE_B;

        #pragma unroll
        for (int ks = 0; ks < 2; ks++) {
            unsigned ah[4][4], al[4][4], bhp[2][4], blp[2][4];
            unsigned kso = stg + ks * 32;
            #pragma unroll
            for (int mf = 0; mf < 4; mf++) {
                ldsm4(ah[mf], aH + kso + mf * 1280);
                ldsm4(al[mf], aL + kso + mf * 1280);
            }
            #pragma unroll
            for (int p = 0; p < 2; p++) {
                ldsm4(bhp[p], bH + kso + p * 1280);
                ldsm4(blp[p], bL + kso + p * 1280);
            }
            #pragma unroll
            for (int mf = 0; mf < 4; mf++)
                #pragma unroll
                for (int nf = 0; nf < 4; nf++) {
                    const unsigned* bhf = &bhp[nf >> 1][(nf & 1) * 2];
                    const unsigned* blf = &blp[nf >> 1][(nf & 1) * 2];
                    mma_bf16(acc[mf][nf], ah[mf], bhf);
                    mma_bf16(acc[mf][nf], ah[mf], blf);
                    mma_bf16(acc[mf][nf], al[mf], bhf);
                }
        }
        __syncthreads();
    }

    #pragma unroll
    for (int mf = 0; mf < 4; mf++) {
        #pragma unroll
        for (int nf = 0; nf < 4; nf++) {
            int row = m0 + wm * 64 + mf * 16 + g;
            int col = n0 + wn * 32 + nf * 8 + 2 * tc;
            *(float2*)(C + (size_t)row * N + col) =
                make_float2(acc[mf][nf][0], acc[mf][nf][1]);
            *(float2*)(C + (size_t)(row + 8) * N + col) =
                make_float2(acc[mf][nf][2], acc[mf][nf][3]);
        }
    }
}

// ---------------------------------------------------------------------------
// RoPE + tf32 pre-rounding of q,k,v in place.
// ---------------------------------------------------------------------------
__global__ __launch_bounds__(256) void rope_kernel(
    float* __restrict__ qkv, const float* __restrict__ freqs)
{
    int idx = blockIdx.x * blockDim.x + threadIdx.x;
    int i    = idx & 63;
    int head = (idx >> 6) % 24;
    int bs   = idx / (64 * 24);
    int s    = bs & (SS - 1);

    if (head < 20) {
        int off = (head < NHH) ? head * HDD : QDIM + (head - NHH) * HDD;
        size_t base = (size_t)bs * QKVD + off + 2 * i;
        float t0 = qkv[base], t1 = qkv[base + 1];
        float f0 = freqs[s * HDD + 2 * i];
        float f1 = freqs[s * HDD + 2 * i + 1];
        qkv[base]     = cvt_tf32f(t0 * f1 - t1 * f0);
        qkv[base + 1] = cvt_tf32f(t0 * f0 + t1 * f1);
    } else {
        size_t base = (size_t)bs * QKVD + QDIM + KVDIM + (head - 20) * HDD + 2 * i;
        qkv[base]     = cvt_tf32f(qkv[base]);
        qkv[base + 1] = cvt_tf32f(qkv[base + 1]);
    }
}

// ---------------------------------------------------------------------------
// Causal flash attention, TF32 mma.sync, FA2-style register softmax
// (unchanged from R6)
// ---------------------------------------------------------------------------
#define QLD 132
#define KLD 132
#define VLD 136
#define SLD 68
#define ATT_SMEM_FLOATS (128*QLD + 2*64*KLD + 64*VLD + 128*SLD)
#define ATT_SMEM_BYTES  (ATT_SMEM_FLOATS * 4)   // 204800

__global__ __launch_bounds__(256, 1) void attn_mma_kernel(
    const float* __restrict__ qkv, float* __restrict__ attn)
{
    extern __shared__ float sm[];
    float* sQ = sm;                    // [128][132]
    float* sK = sQ + 128 * QLD;        // [2][64][132]
    float* sV = sK + 2 * 64 * KLD;     // [64][136]
    float* sP = sV + 64 * VLD;         // [128][68]

    int tid = threadIdx.x;
    int lane = tid & 31, w = tid >> 5;
    int g = lane >> 2, tc = lane & 3;
    int qt = (SS / 128 - 1) - blockIdx.x;
    int h  = blockIdx.y, b = blockIdx.z;
    int kvh = h >> 2;
    int q0 = qt * 128;
    int ktmax = 2 * qt + 1;
    const float scale = 0.08838834764831845f;

    const float* kvbase = qkv + (size_t)b * SS * QKVD + QDIM + kvh * HDD;

    auto issueK = [&](int kt) {
        if (kt <= ktmax) {
            float* dst = sK + (kt & 1) * 64 * KLD;
            const float* src = kvbase + (size_t)kt * 64 * QKVD;
            #pragma unroll
            for (int e = 0; e < 8; e++) {
                int i = tid + e * 256;
                int r = i >> 5, c = (i & 31) << 2;
                cp16(dst + r * KLD + c, src + (size_t)r * QKVD + c);
            }
        }
        asm volatile("cp.async.commit_group;\n");
    };
    auto issueV = [&](int kt) {
        const float* src = kvbase + KVDIM + (size_t)kt * 64 * QKVD;
        #pragma unroll
        for (int e = 0; e < 8; e++) {
            int i = tid + e * 256;
            int r = i >> 5, c = (i & 31) << 2;
            cp16(sV + r * VLD + c, src + (size_t)r * QKVD + c);
        }
        asm volatile("cp.async.commit_group;\n");
    };

    {
        const float* qbase = qkv + ((size_t)(b * SS + q0)) * QKVD + h * HDD;
        #pragma unroll
        for (int e = 0; e < 16; e++) {
            int i = tid + e * 256;
            int r = i >> 5, c = (i & 31) << 2;
            cp16(sQ + r * QLD + c, qbase + (size_t)r * QKVD + c);
        }
        const float* src = kvbase;
        #pragma unroll
        for (int e = 0; e < 8; e++) {
            int i = tid + e * 256;
            int r = i >> 5, c = (i & 31) << 2;
            cp16(sK + r * KLD + c, src + (size_t)r * QKVD + c);
        }
        asm volatile("cp.async.commit_group;\n");
    }

    float m0r = -1e30f, m1r = -1e30f, l0r = 0.f, l1r = 0.f;
    float acc[16][4];
    #pragma unroll
    for (int nf = 0; nf < 16; nf++)
        #pragma unroll
        for (int r = 0; r < 4; r++) acc[nf][r] = 0.f;

    int srow = w * 16 + g;

    for (int kt = 0; kt <= ktmax; kt++) {
        __syncthreads();
        issueV(kt);
        issueK(kt + 1);

        asm volatile("cp.async.wait_group 2;\n");
        __syncthreads();

        const float* sKb = sK + (kt & 1) * 64 * KLD;
        float sacc[8][4] = {};
        const float* Aq = sQ + srow * QLD;
        #pragma unroll
        for (int ks = 0; ks < 16; ks++) {
            const unsigned* ap = (const unsigned*)(Aq + ks * 8 + tc);
            unsigned a[4] = { ap[0], ap[8 * QLD], ap[4], ap[8 * QLD + 4] };
            #pragma unroll
            for (int nf = 0; nf < 8; nf++) {
                const unsigned* bp = (const unsigned*)(sKb + (nf * 8 + g) * KLD + ks * 8 + tc);
                unsigned bb[2] = { bp[0], bp[4] };
                mma_tf32(sacc[nf], a, bb);
            }
        }

        {
            int k0 = kt * 64;
            bool diag = (kt >= 2 * qt);
            #pragma unroll
            for (int nf = 0; nf < 8; nf++) {
                float v0 = sacc[nf][0] * scale, v1 = sacc[nf][1] * scale;
                float v2 = sacc[nf][2] * scale, v3 = sacc[nf][3] * scale;
                if (diag) {
                    int qr = q0 + srow, kc = k0 + nf * 8 + 2 * tc;
                    if (kc     > qr)     v0 = -1e30f;
                    if (kc + 1 > qr)     v1 = -1e30f;
                    if (kc     > qr + 8) v2 = -1e30f;
                    if (kc + 1 > qr + 8) v3 = -1e30f;
                }
                sacc[nf][0] = v0; sacc[nf][1] = v1;
                sacc[nf][2] = v2; sacc[nf][3] = v3;
            }
        }

        float alpha0, alpha1;
        {
            float mx0 = -1e30f, mx1 = -1e30f;
            #pragma unroll
            for (int nf = 0; nf < 8; nf++) {
                mx0 = fmaxf(mx0, fmaxf(sacc[nf][0], sacc[nf][1]));
                mx1 = fmaxf(mx1, fmaxf(sacc[nf][2], sacc[nf][3]));
            }
            mx0 = fmaxf(mx0, __shfl_xor_sync(0xffffffffu, mx0, 1));
            mx0 = fmaxf(mx0, __shfl_xor_sync(0xffffffffu, mx0, 2));
            mx1 = fmaxf(mx1, __shfl_xor_sync(0xffffffffu, mx1, 1));
            mx1 = fmaxf(mx1, __shfl_xor_sync(0xffffffffu, mx1, 2));

            float mn0 = fmaxf(m0r, mx0), mn1 = fmaxf(m1r, mx1);
            alpha0 = __expf(m0r - mn0);
            alpha1 = __expf(m1r - mn1);

            float s0 = 0.f, s1 = 0.f;
            #pragma unroll
            for (int nf = 0; nf < 8; nf++) {
                float p0 = __expf(sacc[nf][0] - mn0);
                float p1 = __expf(sacc[nf][1] - mn0);
                float p2 = __expf(sacc[nf][2] - mn1);
                float p3 = __expf(sacc[nf][3] - mn1);
                s0 += p0 + p1;
                s1 += p2 + p3;
                int col = nf * 8 + 2 * tc;
                *(float2*)(&sP[srow * SLD + col]) =
                    make_float2(cvt_tf32f(p0), cvt_tf32f(p1));
                *(float2*)(&sP[(srow + 8) * SLD + col]) =
                    make_float2(cvt_tf32f(p2), cvt_tf32f(p3));
            }
            s0 += __shfl_xor_sync(0xffffffffu, s0, 1);
            s0 += __shfl_xor_sync(0xffffffffu, s0, 2);
            s1 += __shfl_xor_sync(0xffffffffu, s1, 1);
            s1 += __shfl_xor_sync(0xffffffffu, s1, 2);
            l0r = l0r * alpha0 + s0;
            l1r = l1r * alpha1 + s1;
            m0r = mn0; m1r = mn1;
        }
        __syncwarp();

        #pragma unroll
        for (int nf = 0; nf < 16; nf++) {
            acc[nf][0] *= alpha0; acc[nf][1] *= alpha0;
            acc[nf][2] *= alpha1; acc[nf][3] *= alpha1;
        }

        asm volatile("cp.async.wait_group 1;\n");
        __syncthreads();

        const float* Ap = sP + srow * SLD;
        #pragma unroll
        for (int ks = 0; ks < 8; ks++) {
            const unsigned* ap = (const unsigned*)(Ap + ks * 8 + tc);
            unsigned a[4] = { ap[0], ap[8 * SLD], ap[4], ap[8 * SLD + 4] };
            #pragma unroll
            for (int nf = 0; nf < 16; nf++) {
                const unsigned* bp = (const unsigned*)(sV + (ks * 8 + tc) * VLD + nf * 8 + g);
                unsigned bb[2] = { bp[0], bp[4 * VLD] };
                mma_tf32(acc[nf], a, bb);
            }
        }
    }

    float inv0 = 1.f / l0r;
    float inv1 = 1.f / l1r;
    int row = q0 + srow;
    float* ob = attn + ((size_t)(b * SS + row)) * QDIM + h * HDD;
    #pragma unroll
    for (int nf = 0; nf < 16; nf++) {
        *(float2*)(ob + nf * 8 + 2 * tc) =
            make_float2(acc[nf][0] * inv0, acc[nf][1] * inv0);
        *(float2*)(ob + (size_t)8 * QDIM + nf * 8 + 2 * tc) =
            make_float2(acc[nf][2] * inv1, acc[nf][3] * inv1);
    }
}

// ---------------------------------------------------------------------------
extern "C" void kernel_launch(void* const* d_in, const int* in_sizes, int n_in,
                              void* d_out, int out_size)
{
    (void)in_sizes; (void)n_in; (void)out_size;
    const float* x     = (const float*)d_in[0];
    const float* freqs = (const float*)d_in[1];
    const float* Wqkv  = (const float*)d_in[2];
    const float* Wo    = (const float*)d_in[3];
    float* out = (float*)d_out;

    float *qkvp, *attnp;
    unsigned *xh, *xl, *wqh, *wql, *ah, *al, *woh, *wol;
    cudaGetSymbolAddress((void**)&qkvp, g_qkv);
    cudaGetSymbolAddress((void**)&attnp, g_attn);
    cudaGetSymbolAddress((void**)&xh, g_xh);   cudaGetSymbolAddress((void**)&xl, g_xl);
    cudaGetSymbolAddress((void**)&wqh, g_wqh); cudaGetSymbolAddress((void**)&wql, g_wql);
    cudaGetSymbolAddress((void**)&ah, g_ah);   cudaGetSymbolAddress((void**)&al, g_al);
    cudaGetSymbolAddress((void**)&woh, g_woh); cudaGetSymbolAddress((void**)&wol, g_wol);

    cudaFuncSetAttribute(attn_mma_kernel, cudaFuncAttributeMaxDynamicSharedMemorySize,
                         ATT_SMEM_BYTES);
    cudaFuncSetAttribute(gemm_planes_nt, cudaFuncAttributeMaxDynamicSharedMemorySize,
                         GEMM_SMEM_BYTES);

    // 0) split inputs into bf16 hi/lo planes
    {
        int n4;
        n4 = MROWS * DD / 4;
        split_kernel<<<n4 / 256, 256>>>((const float4*)x, (uint2*)xh, (uint2*)xl, n4);
        n4 = QKVD * DD / 4;
        split_kernel<<<n4 / 256, 256>>>((const float4*)Wqkv, (uint2*)wqh, (uint2*)wql, n4);
        n4 = DD * QDIM / 4;
        split_kernel<<<n4 / 256, 256>>>((const float4*)Wo, (uint2*)woh, (uint2*)wol, n4);
    }

    // 1) QKV projection (bf16x3, ldmatrix)
    gemm_planes_nt<<<dim3(QKVD / 128, MROWS / 128), 256, GEMM_SMEM_BYTES>>>(
        xh, xl, wqh, wql, qkvp, MROWS, QKVD, DD);

    // 2) RoPE + tf32 pre-round
    rope_kernel<<<(BB * SS * 24 * 64) / 256, 256>>>(qkvp, freqs);

    // 3) causal GQA flash attention (tf32, register softmax)
    attn_mma_kernel<<<dim3(SS / 128, NHH, BB), 256, ATT_SMEM_BYTES>>>(qkvp, attnp);

    // 3b) split attention output
    {
        int n4 = MROWS * QDIM / 4;
        split_kernel<<<n4 / 256, 256>>>((const float4*)attnp, (uint2*)ah, (uint2*)al, n4);
    }

    // 4) output projection (bf16x3, ldmatrix)
    gemm_planes_nt<<<dim3(DD / 128, MROWS / 128), 256, GEMM_SMEM_BYTES>>>(
        ah, al, woh, wol, out, MROWS, DD, QDIM);
}